// round 2
// baseline (speedup 1.0000x reference)
#include <cuda_runtime.h>
#include <math.h>

#define Nn   50000
#define Ee   800000
#define NFd  128
#define EFd  16
#define Hd   128
#define OUTC 64
#define IN1  272          // 2*NF + EF

// ---------------- scratch (static device memory; no allocations) ----------------
__device__ float g_h [Nn * Hd];     // aggregated edge messages / layer io
__device__ float g_a [Nn * Hd];     // layer io
__device__ float g_p1[Nn * Hd];     // A^1 v
__device__ float g_p2[Nn * Hd];     // A^2 v
__device__ float g_p3[Nn * Hd];     // A^3 v
__device__ float g_dis[Nn];
__device__ int   g_cnt[Nn];
__device__ int   g_cur[Nn];
__device__ int   g_off[Nn + 1];
__device__ int   g_src[Ee];
__device__ float g_wgt[Ee];

// ---------------- setup kernels ----------------
__global__ void init_kernel() {
    int i = blockIdx.x * blockDim.x + threadIdx.x;
    int stride = gridDim.x * blockDim.x;
    for (int t = i; t < Nn * Hd; t += stride) g_h[t] = 0.0f;
    for (int t = i; t < Nn; t += stride) { g_cnt[t] = 0; g_cur[t] = 0; }
}

__global__ void count_kernel(const int* __restrict__ col) {
    int e = blockIdx.x * blockDim.x + threadIdx.x;
    if (e < Ee) atomicAdd(&g_cnt[col[e]], 1);
}

// single-block exclusive scan of g_cnt -> g_off
__global__ void scan_kernel() {
    __shared__ int sm[1024];
    __shared__ int carry;
    int tid = threadIdx.x;
    if (tid == 0) { carry = 0; g_off[0] = 0; }
    __syncthreads();
    for (int base = 0; base < Nn; base += 1024) {
        int i = base + tid;
        int v = (i < Nn) ? g_cnt[i] : 0;
        sm[tid] = v;
        __syncthreads();
        for (int s = 1; s < 1024; s <<= 1) {
            int t = (tid >= s) ? sm[tid - s] : 0;
            __syncthreads();
            sm[tid] += t;
            __syncthreads();
        }
        if (i < Nn) g_off[i + 1] = carry + sm[tid];
        __syncthreads();
        if (tid == 1023) carry += sm[1023];
        __syncthreads();
    }
}

__global__ void dis_kernel() {
    int i = blockIdx.x * blockDim.x + threadIdx.x;
    if (i < Nn) {
        int c = g_cnt[i];
        g_dis[i] = (c > 0) ? rsqrtf((float)c) : 0.0f;
    }
}

__global__ void scatter_kernel(const int* __restrict__ row, const int* __restrict__ col) {
    int e = blockIdx.x * blockDim.x + threadIdx.x;
    if (e < Ee) {
        int i = col[e], j = row[e];
        int p = atomicAdd(&g_cur[i], 1);
        int o = g_off[i] + p;
        g_src[o] = j;
        g_wgt[o] = g_dis[i] * g_dis[j];
    }
}

// ---------------- edge MLP + aggregate ----------------
// 32 edges/block, 256 threads, 8 threads per edge each owning 16 output cols.
#define SROW 276   // 272 padded (276 % 32 = 20 -> conflict-free broadcast across 4 edges/warp)
#define HROW 132   // 128 padded

__global__ __launch_bounds__(256)
void edge_mlp_kernel(const float* __restrict__ x,
                     const int* __restrict__ row, const int* __restrict__ col,
                     const float* __restrict__ ea,
                     const float* __restrict__ W1, const float* __restrict__ b1,
                     const float* __restrict__ W2, const float* __restrict__ b2,
                     float* __restrict__ hout) {
    __shared__ float s_in[32 * SROW];
    __shared__ int   s_tgt[32];
    int tid = threadIdx.x;
    int e   = tid >> 3;        // 0..31  local edge
    int t8  = tid & 7;         // 0..7   group lane
    int ge  = blockIdx.x * 32 + e;   // Ee % 32 == 0

    int ci = col[ge], cj = row[ge];
    if (t8 == 0) s_tgt[e] = ci;

    float* se = s_in + e * SROW;
    const float4* xi = (const float4*)(x + (size_t)ci * 128);
    const float4* xj = (const float4*)(x + (size_t)cj * 128);
#pragma unroll
    for (int q = 0; q < 4; q++) {
        ((float4*)se)[t8 + q * 8]         = xi[t8 + q * 8];
        ((float4*)(se + 128))[t8 + q * 8] = xj[t8 + q * 8];
    }
    if (t8 < 4) ((float4*)(se + 256))[t8] = ((const float4*)(ea + (size_t)ge * 16))[t8];
    __syncthreads();

    int cg = t8;               // column group: cols cg*16 .. cg*16+15
    float acc[16];
#pragma unroll
    for (int q = 0; q < 16; q++) acc[q] = 0.0f;

#pragma unroll 2
    for (int k = 0; k < IN1; k++) {
        float a = se[k];
        const float4* wr = (const float4*)(W1 + (size_t)k * 128 + cg * 16);
        float4 w0 = wr[0], w1 = wr[1], w2 = wr[2], w3 = wr[3];
        acc[0]  = fmaf(a, w0.x, acc[0]);  acc[1]  = fmaf(a, w0.y, acc[1]);
        acc[2]  = fmaf(a, w0.z, acc[2]);  acc[3]  = fmaf(a, w0.w, acc[3]);
        acc[4]  = fmaf(a, w1.x, acc[4]);  acc[5]  = fmaf(a, w1.y, acc[5]);
        acc[6]  = fmaf(a, w1.z, acc[6]);  acc[7]  = fmaf(a, w1.w, acc[7]);
        acc[8]  = fmaf(a, w2.x, acc[8]);  acc[9]  = fmaf(a, w2.y, acc[9]);
        acc[10] = fmaf(a, w2.z, acc[10]); acc[11] = fmaf(a, w2.w, acc[11]);
        acc[12] = fmaf(a, w3.x, acc[12]); acc[13] = fmaf(a, w3.y, acc[13]);
        acc[14] = fmaf(a, w3.z, acc[14]); acc[15] = fmaf(a, w3.w, acc[15]);
    }
    __syncthreads();           // everyone done reading s_in

    // hidden overlays s_in
    float* s_hid = s_in;
    float* he = s_hid + e * HROW;
#pragma unroll
    for (int q = 0; q < 16; q++) {
        float v = acc[q] + b1[cg * 16 + q];
        he[cg * 16 + q] = fmaxf(v, 0.0f);
    }
    __syncthreads();

    float acc2[16];
#pragma unroll
    for (int q = 0; q < 16; q++) acc2[q] = 0.0f;

#pragma unroll 2
    for (int k = 0; k < 128; k++) {
        float a = he[k];
        const float4* wr = (const float4*)(W2 + (size_t)k * 128 + cg * 16);
        float4 w0 = wr[0], w1 = wr[1], w2 = wr[2], w3 = wr[3];
        acc2[0]  = fmaf(a, w0.x, acc2[0]);  acc2[1]  = fmaf(a, w0.y, acc2[1]);
        acc2[2]  = fmaf(a, w0.z, acc2[2]);  acc2[3]  = fmaf(a, w0.w, acc2[3]);
        acc2[4]  = fmaf(a, w1.x, acc2[4]);  acc2[5]  = fmaf(a, w1.y, acc2[5]);
        acc2[6]  = fmaf(a, w1.z, acc2[6]);  acc2[7]  = fmaf(a, w1.w, acc2[7]);
        acc2[8]  = fmaf(a, w2.x, acc2[8]);  acc2[9]  = fmaf(a, w2.y, acc2[9]);
        acc2[10] = fmaf(a, w2.z, acc2[10]); acc2[11] = fmaf(a, w2.w, acc2[11]);
        acc2[12] = fmaf(a, w3.x, acc2[12]); acc2[13] = fmaf(a, w3.y, acc2[13]);
        acc2[14] = fmaf(a, w3.z, acc2[14]); acc2[15] = fmaf(a, w3.w, acc2[15]);
    }

    int tgt = s_tgt[e];
    float* hp = hout + (size_t)tgt * 128 + cg * 16;
#pragma unroll
    for (int q = 0; q < 16; q++)
        atomicAdd(hp + q, acc2[q] + b2[cg * 16 + q]);
}

// ---------------- SpMM: out_i = sum_e w_e * vin[src_e], CSR, warp per node ----------------
__global__ __launch_bounds__(128)
void spmm_kernel(const float* __restrict__ vin, float* __restrict__ vout) {
    int node = (blockIdx.x * blockDim.x + threadIdx.x) >> 5;
    int lane = threadIdx.x & 31;
    if (node >= Nn) return;
    int s = g_off[node], e = g_off[node + 1];
    float4 acc = make_float4(0.f, 0.f, 0.f, 0.f);
    int idx = s;
    for (; idx + 1 < e; idx += 2) {
        int   j0 = g_src[idx],     j1 = g_src[idx + 1];
        float w0 = g_wgt[idx],     w1 = g_wgt[idx + 1];
        float4 v0 = ((const float4*)(vin + (size_t)j0 * 128))[lane];
        float4 v1 = ((const float4*)(vin + (size_t)j1 * 128))[lane];
        acc.x = fmaf(w0, v0.x, acc.x); acc.y = fmaf(w0, v0.y, acc.y);
        acc.z = fmaf(w0, v0.z, acc.z); acc.w = fmaf(w0, v0.w, acc.w);
        acc.x = fmaf(w1, v1.x, acc.x); acc.y = fmaf(w1, v1.y, acc.y);
        acc.z = fmaf(w1, v1.z, acc.z); acc.w = fmaf(w1, v1.w, acc.w);
    }
    if (idx < e) {
        int   j0 = g_src[idx];
        float w0 = g_wgt[idx];
        float4 v0 = ((const float4*)(vin + (size_t)j0 * 128))[lane];
        acc.x = fmaf(w0, v0.x, acc.x); acc.y = fmaf(w0, v0.y, acc.y);
        acc.z = fmaf(w0, v0.z, acc.z); acc.w = fmaf(w0, v0.w, acc.w);
    }
    ((float4*)(vout + (size_t)node * 128))[lane] = acc;
}

// ---------------- fused 4-way GEMM: out = A0 W0 + A1 W1 + A2 W2 + A3 W3 + b (opt ReLU) ----
// 64-row tiles, 256 threads. W read from global (L1/L2 hot). C = 128 or 64.
template <int C, int RELU>
__global__ __launch_bounds__(256)
void gemm4_kernel(const float* __restrict__ A0, const float* __restrict__ A1,
                  const float* __restrict__ A2, const float* __restrict__ A3,
                  const float* __restrict__ W,     // [4][128][C]
                  const float* __restrict__ bias,  // [C]
                  float* __restrict__ out) {
    constexpr int NCQ = C / 4;                 // column quads
    constexpr int NRG = 256 / NCQ;             // row groups
    constexpr int R   = 64 / NRG;              // rows per thread
    __shared__ float s_a[64 * 128];

    int tid  = threadIdx.x;
    int row0 = blockIdx.x * 64;
    int cq   = tid % NCQ;
    int rg   = tid / NCQ;

    float4 acc[R];
#pragma unroll
    for (int r = 0; r < R; r++) acc[r] = make_float4(0.f, 0.f, 0.f, 0.f);

    const float* As[4] = {A0, A1, A2, A3};
    for (int g = 0; g < 4; g++) {
        __syncthreads();
        const float* A = As[g];
#pragma unroll
        for (int q = 0; q < 8; q++) {
            int idx = tid + q * 256;           // float4 index, 0..2047
            int r   = idx >> 5;
            int c4  = idx & 31;
            int grow = row0 + r;
            float4 v = (grow < Nn) ? ((const float4*)(A + (size_t)grow * 128))[c4]
                                   : make_float4(0.f, 0.f, 0.f, 0.f);
            ((float4*)s_a)[idx] = v;
        }
        __syncthreads();

        const float* Wg = W + (size_t)g * 128 * C;
#pragma unroll 2
        for (int k = 0; k < 128; k++) {
            float4 w = __ldg((const float4*)(Wg + (size_t)k * C) + cq);
#pragma unroll
            for (int r = 0; r < R; r++) {
                float a = s_a[(rg * R + r) * 128 + k];
                acc[r].x = fmaf(a, w.x, acc[r].x);
                acc[r].y = fmaf(a, w.y, acc[r].y);
                acc[r].z = fmaf(a, w.z, acc[r].z);
                acc[r].w = fmaf(a, w.w, acc[r].w);
            }
        }
    }

    float4 bv = __ldg((const float4*)bias + cq);
#pragma unroll
    for (int r = 0; r < R; r++) {
        int grow = row0 + rg * R + r;
        if (grow < Nn) {
            float4 o;
            o.x = acc[r].x + bv.x; o.y = acc[r].y + bv.y;
            o.z = acc[r].z + bv.z; o.w = acc[r].w + bv.w;
            if (RELU) {
                o.x = fmaxf(o.x, 0.f); o.y = fmaxf(o.y, 0.f);
                o.z = fmaxf(o.z, 0.f); o.w = fmaxf(o.w, 0.f);
            }
            ((float4*)(out + (size_t)grow * C))[cq] = o;
        }
    }
}

// ---------------- launch ----------------
extern "C" void kernel_launch(void* const* d_in, const int* in_sizes, int n_in,
                              void* d_out, int out_size) {
    const float* x   = (const float*)d_in[0];
    const int*   ei  = (const int*)  d_in[1];
    const float* ea  = (const float*)d_in[2];
    const float* W1  = (const float*)d_in[3];
    const float* b1  = (const float*)d_in[4];
    const float* W2  = (const float*)d_in[5];
    const float* b2  = (const float*)d_in[6];
    const float* t0W = (const float*)d_in[7];
    const float* t0b = (const float*)d_in[8];
    const float* t1W = (const float*)d_in[9];
    const float* t1b = (const float*)d_in[10];
    const float* t2W = (const float*)d_in[11];
    const float* t2b = (const float*)d_in[12];
    const int* row = ei;        // source j
    const int* col = ei + Ee;   // target i

    float *ph, *pa, *pp1, *pp2, *pp3;
    cudaGetSymbolAddress((void**)&ph,  g_h);
    cudaGetSymbolAddress((void**)&pa,  g_a);
    cudaGetSymbolAddress((void**)&pp1, g_p1);
    cudaGetSymbolAddress((void**)&pp2, g_p2);
    cudaGetSymbolAddress((void**)&pp3, g_p3);

    // graph prep
    init_kernel<<<4096, 256>>>();
    count_kernel<<<Ee / 256, 256>>>(col);
    scan_kernel<<<1, 1024>>>();
    dis_kernel<<<(Nn + 255) / 256, 256>>>();
    scatter_kernel<<<Ee / 256, 256>>>(row, col);

    // edge MLP -> aggregated h
    edge_mlp_kernel<<<Ee / 32, 256>>>(x, row, col, ea, W1, b1, W2, b2, ph);

    const int SPMM_GRID = (Nn + 3) / 4;
    const int GEMM_GRID = (Nn + 63) / 64;

    // layer 0: h -> a  (ReLU)
    spmm_kernel<<<SPMM_GRID, 128>>>(ph,  pp1);
    spmm_kernel<<<SPMM_GRID, 128>>>(pp1, pp2);
    spmm_kernel<<<SPMM_GRID, 128>>>(pp2, pp3);
    gemm4_kernel<128, 1><<<GEMM_GRID, 256>>>(ph, pp1, pp2, pp3, t0W, t0b, pa);

    // layer 1: a -> h  (ReLU)
    spmm_kernel<<<SPMM_GRID, 128>>>(pa,  pp1);
    spmm_kernel<<<SPMM_GRID, 128>>>(pp1, pp2);
    spmm_kernel<<<SPMM_GRID, 128>>>(pp2, pp3);
    gemm4_kernel<128, 1><<<GEMM_GRID, 256>>>(pa, pp1, pp2, pp3, t1W, t1b, ph);

    // layer 2: h -> out (no ReLU, C=64)
    spmm_kernel<<<SPMM_GRID, 128>>>(ph,  pp1);
    spmm_kernel<<<SPMM_GRID, 128>>>(pp1, pp2);
    spmm_kernel<<<SPMM_GRID, 128>>>(pp2, pp3);
    gemm4_kernel<64, 0><<<GEMM_GRID, 256>>>(ph, pp1, pp2, pp3, t2W, t2b, (float*)d_out);
}

// round 3
// speedup vs baseline: 6.0915x; 6.0915x over previous
#include <cuda_runtime.h>
#include <math.h>

typedef unsigned long long ull;

#define Nn   50000
#define Ee   800000
#define Hd   128
#define OUTC 64

// ---------------- scratch (static device memory; no allocations) ----------------
__device__ float g_h [Nn * Hd];
__device__ float g_a [Nn * Hd];
__device__ float g_p1[Nn * Hd];
__device__ float g_p2[Nn * Hd];
__device__ float g_p3[Nn * Hd];
__device__ float g_dis[Nn];
__device__ int   g_cnt[Nn];
__device__ int   g_cur[Nn];
__device__ int   g_off[Nn + 1];
__device__ int   g_src[Ee];
__device__ float g_wgt[Ee];

// ---------------- setup kernels ----------------
__global__ void init_kernel() {
    int i = blockIdx.x * blockDim.x + threadIdx.x;
    int stride = gridDim.x * blockDim.x;
    for (int t = i; t < Nn * Hd; t += stride) g_h[t] = 0.0f;
    for (int t = i; t < Nn; t += stride) { g_cnt[t] = 0; g_cur[t] = 0; }
}

__global__ void count_kernel(const int* __restrict__ col) {
    int e = blockIdx.x * blockDim.x + threadIdx.x;
    if (e < Ee) atomicAdd(&g_cnt[col[e]], 1);
}

__global__ void scan_kernel() {
    __shared__ int sm[1024];
    __shared__ int carry;
    int tid = threadIdx.x;
    if (tid == 0) { carry = 0; g_off[0] = 0; }
    __syncthreads();
    for (int base = 0; base < Nn; base += 1024) {
        int i = base + tid;
        int v = (i < Nn) ? g_cnt[i] : 0;
        sm[tid] = v;
        __syncthreads();
        for (int s = 1; s < 1024; s <<= 1) {
            int t = (tid >= s) ? sm[tid - s] : 0;
            __syncthreads();
            sm[tid] += t;
            __syncthreads();
        }
        if (i < Nn) g_off[i + 1] = carry + sm[tid];
        __syncthreads();
        if (tid == 1023) carry += sm[1023];
        __syncthreads();
    }
}

__global__ void dis_kernel() {
    int i = blockIdx.x * blockDim.x + threadIdx.x;
    if (i < Nn) {
        int c = g_cnt[i];
        g_dis[i] = (c > 0) ? rsqrtf((float)c) : 0.0f;
    }
}

__global__ void scatter_kernel(const int* __restrict__ row, const int* __restrict__ col) {
    int e = blockIdx.x * blockDim.x + threadIdx.x;
    if (e < Ee) {
        int i = col[e], j = row[e];
        int p = atomicAdd(&g_cur[i], 1);
        int o = g_off[i] + p;
        g_src[o] = j;
        g_wgt[o] = g_dis[i] * g_dis[j];
    }
}

// ---------------- packed f32x2 helpers ----------------
__device__ __forceinline__ ull pk2(float a) {
    ull d; unsigned int u = __float_as_uint(a);
    asm("mov.b64 %0, {%1, %1};" : "=l"(d) : "r"(u));
    return d;
}
__device__ __forceinline__ ull fma2(ull a, ull b, ull c) {
    ull d;
    asm("fma.rn.f32x2 %0, %1, %2, %3;" : "=l"(d) : "l"(a), "l"(b), "l"(c));
    return d;
}
__device__ __forceinline__ float2 up2(ull v) {
    unsigned int lo, hi;
    asm("mov.b64 {%0, %1}, %2;" : "=r"(lo), "=r"(hi) : "l"(v));
    return make_float2(__uint_as_float(lo), __uint_as_float(hi));
}

// ---------------- edge MLP: smem-tiled GEMM, 128 edges/block ----------------
// phase A: hid[128e][128] = relu([x_i | x_j | ea] (272) * W1 + b1)
// phase B: msg[128e][128] = hid * W2 + b2 -> atomicAdd into hout[target]
#define ST 132          // smem row stride (floats)
#define EDGE_SMEM_BYTES ((128 * ST + 16 * ST + 16 * ST) * 4 + 256 * 4)

__global__ void __launch_bounds__(256, 2)
edge_mlp_kernel(const float* __restrict__ x,
                const int* __restrict__ row, const int* __restrict__ col,
                const float* __restrict__ ea,
                const float* __restrict__ W1, const float* __restrict__ b1,
                const float* __restrict__ W2, const float* __restrict__ b2,
                float* __restrict__ hout) {
    extern __shared__ float smf[];
    float* sHT = smf;                 // [128 col][ST]  hidden^T
    float* sA  = sHT + 128 * ST;      // [16 k][ST]     input tile (k-major, edge contiguous)
    float* sB  = sA + 16 * ST;        // [16 k][ST]     weight tile
    int* sCI   = (int*)(sB + 16 * ST);
    int* sCJ   = sCI + 128;

    const int tid = threadIdx.x;
    const int tx  = tid & 15;         // col group: cols tx*8 .. tx*8+7
    const int ty  = tid >> 4;         // row group: edges ty*8 .. ty*8+7
    const int e0  = blockIdx.x * 128; // Ee % 128 == 0
    const int er  = tid >> 1;         // edge this thread gathers
    const int hh  = tid & 1;          // k-half (0 or 8)
    const int wk  = tid >> 5;         // weight row within half-tile
    const int wc  = (tid & 31) * 4;   // weight col

    if (tid < 128) { sCI[tid] = col[e0 + tid]; sCJ[tid] = row[e0 + tid]; }
    __syncthreads();

    ull acc[8][4];
#pragma unroll
    for (int r = 0; r < 8; r++)
#pragma unroll
        for (int p = 0; p < 4; p++) acc[r][p] = 0ULL;

    // ---------- phase A: K=272 in 17 chunks of 16 ----------
    for (int c = 0; c < 17; c++) {
        const float* abase;
        if (c < 8)       abase = x + (size_t)sCI[er] * 128 + c * 16 + hh * 8;
        else if (c < 16) abase = x + (size_t)sCJ[er] * 128 + (c - 8) * 16 + hh * 8;
        else             abase = ea + (size_t)(e0 + er) * 16 + hh * 8;
        float4 f0 = *(const float4*)abase;
        float4 f1 = *(const float4*)(abase + 4);
        float4 w0 = *(const float4*)(W1 + (size_t)(c * 16 + wk) * 128 + wc);
        float4 w1 = *(const float4*)(W1 + (size_t)(c * 16 + 8 + wk) * 128 + wc);
        __syncthreads();   // previous chunk fully consumed
        sA[(hh * 8 + 0) * ST + er] = f0.x;
        sA[(hh * 8 + 1) * ST + er] = f0.y;
        sA[(hh * 8 + 2) * ST + er] = f0.z;
        sA[(hh * 8 + 3) * ST + er] = f0.w;
        sA[(hh * 8 + 4) * ST + er] = f1.x;
        sA[(hh * 8 + 5) * ST + er] = f1.y;
        sA[(hh * 8 + 6) * ST + er] = f1.z;
        sA[(hh * 8 + 7) * ST + er] = f1.w;
        *(float4*)&sB[wk * ST + wc]       = w0;
        *(float4*)&sB[(wk + 8) * ST + wc] = w1;
        __syncthreads();
#pragma unroll
        for (int kk = 0; kk < 16; kk++) {
            float4 a0 = *(const float4*)&sA[kk * ST + ty * 8];
            float4 a1 = *(const float4*)&sA[kk * ST + ty * 8 + 4];
            ulonglong2 bx = *(const ulonglong2*)&sB[kk * ST + tx * 8];
            ulonglong2 by = *(const ulonglong2*)&sB[kk * ST + tx * 8 + 4];
            ull aa[8] = { pk2(a0.x), pk2(a0.y), pk2(a0.z), pk2(a0.w),
                          pk2(a1.x), pk2(a1.y), pk2(a1.z), pk2(a1.w) };
#pragma unroll
            for (int r = 0; r < 8; r++) {
                acc[r][0] = fma2(aa[r], bx.x, acc[r][0]);
                acc[r][1] = fma2(aa[r], bx.y, acc[r][1]);
                acc[r][2] = fma2(aa[r], by.x, acc[r][2]);
                acc[r][3] = fma2(aa[r], by.y, acc[r][3]);
            }
        }
    }

    // ---------- phase A epilogue: bias + relu, store hidden^T ----------
    {
        float bv[8];
#pragma unroll
        for (int j = 0; j < 8; j++) bv[j] = b1[tx * 8 + j];
#pragma unroll
        for (int p = 0; p < 4; p++) {
            float2 v[8];
#pragma unroll
            for (int r = 0; r < 8; r++) v[r] = up2(acc[r][p]);
            float bx0 = bv[2 * p], bx1 = bv[2 * p + 1];
            float4 lo0 = make_float4(fmaxf(v[0].x + bx0, 0.f), fmaxf(v[1].x + bx0, 0.f),
                                     fmaxf(v[2].x + bx0, 0.f), fmaxf(v[3].x + bx0, 0.f));
            float4 hi0 = make_float4(fmaxf(v[4].x + bx0, 0.f), fmaxf(v[5].x + bx0, 0.f),
                                     fmaxf(v[6].x + bx0, 0.f), fmaxf(v[7].x + bx0, 0.f));
            float4 lo1 = make_float4(fmaxf(v[0].y + bx1, 0.f), fmaxf(v[1].y + bx1, 0.f),
                                     fmaxf(v[2].y + bx1, 0.f), fmaxf(v[3].y + bx1, 0.f));
            float4 hi1 = make_float4(fmaxf(v[4].y + bx1, 0.f), fmaxf(v[5].y + bx1, 0.f),
                                     fmaxf(v[6].y + bx1, 0.f), fmaxf(v[7].y + bx1, 0.f));
            int c0 = tx * 8 + 2 * p;
            *(float4*)&sHT[c0 * ST + ty * 8]           = lo0;
            *(float4*)&sHT[c0 * ST + ty * 8 + 4]       = hi0;
            *(float4*)&sHT[(c0 + 1) * ST + ty * 8]     = lo1;
            *(float4*)&sHT[(c0 + 1) * ST + ty * 8 + 4] = hi1;
        }
    }

    // ---------- phase B: msg = hid * W2, K=128 in 8 chunks ----------
#pragma unroll
    for (int r = 0; r < 8; r++)
#pragma unroll
        for (int p = 0; p < 4; p++) acc[r][p] = 0ULL;

    for (int c = 0; c < 8; c++) {
        float4 w0 = *(const float4*)(W2 + (size_t)(c * 16 + wk) * 128 + wc);
        float4 w1 = *(const float4*)(W2 + (size_t)(c * 16 + 8 + wk) * 128 + wc);
        __syncthreads();   // sB consumed; also (c==0) sHT stores complete
        *(float4*)&sB[wk * ST + wc]       = w0;
        *(float4*)&sB[(wk + 8) * ST + wc] = w1;
        __syncthreads();
#pragma unroll
        for (int kk = 0; kk < 16; kk++) {
            int k = c * 16 + kk;
            float4 a0 = *(const float4*)&sHT[k * ST + ty * 8];
            float4 a1 = *(const float4*)&sHT[k * ST + ty * 8 + 4];
            ulonglong2 bx = *(const ulonglong2*)&sB[kk * ST + tx * 8];
            ulonglong2 by = *(const ulonglong2*)&sB[kk * ST + tx * 8 + 4];
            ull aa[8] = { pk2(a0.x), pk2(a0.y), pk2(a0.z), pk2(a0.w),
                          pk2(a1.x), pk2(a1.y), pk2(a1.z), pk2(a1.w) };
#pragma unroll
            for (int r = 0; r < 8; r++) {
                acc[r][0] = fma2(aa[r], bx.x, acc[r][0]);
                acc[r][1] = fma2(aa[r], bx.y, acc[r][1]);
                acc[r][2] = fma2(aa[r], by.x, acc[r][2]);
                acc[r][3] = fma2(aa[r], by.y, acc[r][3]);
            }
        }
    }

    // ---------- phase B epilogue: bias + atomic scatter ----------
    {
        float bv[8];
#pragma unroll
        for (int j = 0; j < 8; j++) bv[j] = b2[tx * 8 + j];
#pragma unroll
        for (int r = 0; r < 8; r++) {
            int tgt = sCI[ty * 8 + r];
            float* hp = hout + (size_t)tgt * 128 + tx * 8;
#pragma unroll
            for (int p = 0; p < 4; p++) {
                float2 v = up2(acc[r][p]);
                atomicAdd(hp + 2 * p,     v.x + bv[2 * p]);
                atomicAdd(hp + 2 * p + 1, v.y + bv[2 * p + 1]);
            }
        }
    }
}

// ---------------- SpMM: out_i = sum_e w_e * vin[src_e], CSR, warp per node ----------------
__global__ void __launch_bounds__(128)
spmm_kernel(const float* __restrict__ vin, float* __restrict__ vout) {
    int node = (blockIdx.x * blockDim.x + threadIdx.x) >> 5;
    int lane = threadIdx.x & 31;
    if (node >= Nn) return;
    int s = g_off[node], e = g_off[node + 1];
    float4 acc = make_float4(0.f, 0.f, 0.f, 0.f);
    int idx = s;
    for (; idx + 1 < e; idx += 2) {
        int   j0 = g_src[idx],     j1 = g_src[idx + 1];
        float w0 = g_wgt[idx],     w1 = g_wgt[idx + 1];
        float4 v0 = ((const float4*)(vin + (size_t)j0 * 128))[lane];
        float4 v1 = ((const float4*)(vin + (size_t)j1 * 128))[lane];
        acc.x = fmaf(w0, v0.x, acc.x); acc.y = fmaf(w0, v0.y, acc.y);
        acc.z = fmaf(w0, v0.z, acc.z); acc.w = fmaf(w0, v0.w, acc.w);
        acc.x = fmaf(w1, v1.x, acc.x); acc.y = fmaf(w1, v1.y, acc.y);
        acc.z = fmaf(w1, v1.z, acc.z); acc.w = fmaf(w1, v1.w, acc.w);
    }
    if (idx < e) {
        int   j0 = g_src[idx];
        float w0 = g_wgt[idx];
        float4 v0 = ((const float4*)(vin + (size_t)j0 * 128))[lane];
        acc.x = fmaf(w0, v0.x, acc.x); acc.y = fmaf(w0, v0.y, acc.y);
        acc.z = fmaf(w0, v0.z, acc.z); acc.w = fmaf(w0, v0.w, acc.w);
    }
    ((float4*)(vout + (size_t)node * 128))[lane] = acc;
}

// ---------------- fused 4-way GEMM: out = sum_g A_g W_g + b (opt ReLU) ----------------
template <int C, int RELU>
__global__ void __launch_bounds__(256)
gemm4_kernel(const float* __restrict__ A0, const float* __restrict__ A1,
             const float* __restrict__ A2, const float* __restrict__ A3,
             const float* __restrict__ W,     // [4][128][C]
             const float* __restrict__ bias,  // [C]
             float* __restrict__ out) {
    constexpr int NCQ = C / 4;
    constexpr int NRG = 256 / NCQ;
    constexpr int R   = 64 / NRG;
    __shared__ float s_a[64 * 128];

    int tid  = threadIdx.x;
    int row0 = blockIdx.x * 64;
    int cq   = tid % NCQ;
    int rg   = tid / NCQ;

    float4 acc[R];
#pragma unroll
    for (int r = 0; r < R; r++) acc[r] = make_float4(0.f, 0.f, 0.f, 0.f);

    const float* As[4] = {A0, A1, A2, A3};
    for (int g = 0; g < 4; g++) {
        __syncthreads();
        const float* A = As[g];
#pragma unroll
        for (int q = 0; q < 8; q++) {
            int idx = tid + q * 256;
            int r   = idx >> 5;
            int c4  = idx & 31;
            int grow = row0 + r;
            float4 v = (grow < Nn) ? ((const float4*)(A + (size_t)grow * 128))[c4]
                                   : make_float4(0.f, 0.f, 0.f, 0.f);
            ((float4*)s_a)[idx] = v;
        }
        __syncthreads();

        const float* Wg = W + (size_t)g * 128 * C;
#pragma unroll 2
        for (int k = 0; k < 128; k++) {
            float4 w = __ldg((const float4*)(Wg + (size_t)k * C) + cq);
#pragma unroll
            for (int r = 0; r < R; r++) {
                float a = s_a[(rg * R + r) * 128 + k];
                acc[r].x = fmaf(a, w.x, acc[r].x);
                acc[r].y = fmaf(a, w.y, acc[r].y);
                acc[r].z = fmaf(a, w.z, acc[r].z);
                acc[r].w = fmaf(a, w.w, acc[r].w);
            }
        }
    }

    float4 bv = __ldg((const float4*)bias + cq);
#pragma unroll
    for (int r = 0; r < R; r++) {
        int grow = row0 + rg * R + r;
        if (grow < Nn) {
            float4 o;
            o.x = acc[r].x + bv.x; o.y = acc[r].y + bv.y;
            o.z = acc[r].z + bv.z; o.w = acc[r].w + bv.w;
            if (RELU) {
                o.x = fmaxf(o.x, 0.f); o.y = fmaxf(o.y, 0.f);
                o.z = fmaxf(o.z, 0.f); o.w = fmaxf(o.w, 0.f);
            }
            ((float4*)(out + (size_t)grow * C))[cq] = o;
        }
    }
}

// ---------------- launch ----------------
extern "C" void kernel_launch(void* const* d_in, const int* in_sizes, int n_in,
                              void* d_out, int out_size) {
    const float* x   = (const float*)d_in[0];
    const int*   ei  = (const int*)  d_in[1];
    const float* ea  = (const float*)d_in[2];
    const float* W1  = (const float*)d_in[3];
    const float* b1  = (const float*)d_in[4];
    const float* W2  = (const float*)d_in[5];
    const float* b2  = (const float*)d_in[6];
    const float* t0W = (const float*)d_in[7];
    const float* t0b = (const float*)d_in[8];
    const float* t1W = (const float*)d_in[9];
    const float* t1b = (const float*)d_in[10];
    const float* t2W = (const float*)d_in[11];
    const float* t2b = (const float*)d_in[12];
    const int* row = ei;        // source j
    const int* col = ei + Ee;   // target i

    float *ph, *pa, *pp1, *pp2, *pp3;
    cudaGetSymbolAddress((void**)&ph,  g_h);
    cudaGetSymbolAddress((void**)&pa,  g_a);
    cudaGetSymbolAddress((void**)&pp1, g_p1);
    cudaGetSymbolAddress((void**)&pp2, g_p2);
    cudaGetSymbolAddress((void**)&pp3, g_p3);

    cudaFuncSetAttribute(edge_mlp_kernel,
                         cudaFuncAttributeMaxDynamicSharedMemorySize,
                         EDGE_SMEM_BYTES);

    // prep (edge_mlp placed 4th so it lands in the ncu-profiled slot)
    init_kernel<<<4096, 256>>>();
    count_kernel<<<Ee / 256, 256>>>(col);
    scan_kernel<<<1, 1024>>>();
    edge_mlp_kernel<<<Ee / 128, 256, EDGE_SMEM_BYTES>>>(x, row, col, ea, W1, b1, W2, b2, ph);
    dis_kernel<<<(Nn + 255) / 256, 256>>>();
    scatter_kernel<<<Ee / 256, 256>>>(row, col);

    const int SPMM_GRID = (Nn + 3) / 4;
    const int GEMM_GRID = (Nn + 63) / 64;

    // layer 0: h -> a  (ReLU)
    spmm_kernel<<<SPMM_GRID, 128>>>(ph,  pp1);
    spmm_kernel<<<SPMM_GRID, 128>>>(pp1, pp2);
    spmm_kernel<<<SPMM_GRID, 128>>>(pp2, pp3);
    gemm4_kernel<128, 1><<<GEMM_GRID, 256>>>(ph, pp1, pp2, pp3, t0W, t0b, pa);

    // layer 1: a -> h  (ReLU)
    spmm_kernel<<<SPMM_GRID, 128>>>(pa,  pp1);
    spmm_kernel<<<SPMM_GRID, 128>>>(pp1, pp2);
    spmm_kernel<<<SPMM_GRID, 128>>>(pp2, pp3);
    gemm4_kernel<128, 1><<<GEMM_GRID, 256>>>(pa, pp1, pp2, pp3, t1W, t1b, ph);

    // layer 2: h -> out (no ReLU, C=64)
    spmm_kernel<<<SPMM_GRID, 128>>>(ph,  pp1);
    spmm_kernel<<<SPMM_GRID, 128>>>(pp1, pp2);
    spmm_kernel<<<SPMM_GRID, 128>>>(pp2, pp3);
    gemm4_kernel<64, 0><<<GEMM_GRID, 256>>>(ph, pp1, pp2, pp3, t2W, t2b, (float*)d_out);
}

// round 5
// speedup vs baseline: 9.3155x; 1.5293x over previous
#include <cuda_runtime.h>
#include <math.h>

typedef unsigned long long ull;

#define Nn   50000
#define Ee   800000
#define Hd   128
#define OUTC 64

// ---------------- scratch (static device memory; no allocations) ----------------
__device__ float g_h [Nn * Hd];
__device__ float g_a [Nn * Hd];
__device__ float g_p1[Nn * Hd];   // also P = x*W1a before spmm stage
__device__ float g_p2[Nn * Hd];   // also Q = x*W1b before spmm stage
__device__ float g_p3[Nn * Hd];
__device__ float g_dis[Nn];
__device__ int   g_cnt[Nn];
__device__ int   g_cur[Nn];
__device__ int   g_off[Nn + 1];
__device__ int   g_src[Ee];
__device__ float g_wgt[Ee];

// ---------------- packed f32x2 helpers ----------------
__device__ __forceinline__ ull pk2(float a) {
    ull d; unsigned int u = __float_as_uint(a);
    asm("mov.b64 %0, {%1, %1};" : "=l"(d) : "r"(u));
    return d;
}
__device__ __forceinline__ ull pack2(float lo, float hi) {
    ull d;
    asm("mov.b64 %0, {%1, %2};" : "=l"(d) : "r"(__float_as_uint(lo)), "r"(__float_as_uint(hi)));
    return d;
}
__device__ __forceinline__ ull fma2(ull a, ull b, ull c) {
    ull d;
    asm("fma.rn.f32x2 %0, %1, %2, %3;" : "=l"(d) : "l"(a), "l"(b), "l"(c));
    return d;
}
__device__ __forceinline__ float2 up2(ull v) {
    unsigned int lo, hi;
    asm("mov.b64 {%0, %1}, %2;" : "=r"(lo), "=r"(hi) : "l"(v));
    return make_float2(__uint_as_float(lo), __uint_as_float(hi));
}

// ---------------- setup kernels ----------------
__global__ void init_kernel() {
    int i = blockIdx.x * blockDim.x + threadIdx.x;
    int stride = gridDim.x * blockDim.x;
    for (int t = i; t < Nn * Hd; t += stride) g_h[t] = 0.0f;
    for (int t = i; t < Nn; t += stride) { g_cnt[t] = 0; g_cur[t] = 0; }
}

__global__ void count_kernel(const int* __restrict__ col) {
    int e = blockIdx.x * blockDim.x + threadIdx.x;
    if (e < Ee) atomicAdd(&g_cnt[col[e]], 1);
}

__global__ void scan_kernel() {
    __shared__ int sm[1024];
    __shared__ int carry;
    int tid = threadIdx.x;
    if (tid == 0) { carry = 0; g_off[0] = 0; }
    __syncthreads();
    for (int base = 0; base < Nn; base += 1024) {
        int i = base + tid;
        int v = (i < Nn) ? g_cnt[i] : 0;
        sm[tid] = v;
        __syncthreads();
        for (int s = 1; s < 1024; s <<= 1) {
            int t = (tid >= s) ? sm[tid - s] : 0;
            __syncthreads();
            sm[tid] += t;
            __syncthreads();
        }
        if (i < Nn) g_off[i + 1] = carry + sm[tid];
        __syncthreads();
        if (tid == 1023) carry += sm[1023];
        __syncthreads();
    }
}

__global__ void dis_kernel() {
    int i = blockIdx.x * blockDim.x + threadIdx.x;
    if (i < Nn) {
        int c = g_cnt[i];
        g_dis[i] = (c > 0) ? rsqrtf((float)c) : 0.0f;
    }
}

__global__ void scatter_kernel(const int* __restrict__ row, const int* __restrict__ col) {
    int e = blockIdx.x * blockDim.x + threadIdx.x;
    if (e < Ee) {
        int i = col[e], j = row[e];
        int p = atomicAdd(&g_cur[i], 1);
        int o = g_off[i] + p;
        g_src[o] = j;
        g_wgt[o] = g_dis[i] * g_dis[j];
    }
}

// ---------------- generic dense GEMM: out = sum_{g<G} A_g W_g (+bias)(+relu) -----
// 64-row tiles, 256 threads, s_a stored k-major transposed so FFMA2 row-pairs
// come straight out of LDS.128. W streamed from L1/L2.
#define SAS 68
template <int G, int C, int RELU, int BIAS>
__global__ void __launch_bounds__(256)
gemm_kernel(const float* __restrict__ A0, const float* __restrict__ A1,
            const float* __restrict__ A2, const float* __restrict__ A3,
            const float* __restrict__ W,     // [G][128][C]
            const float* __restrict__ bias,  // [C] (if BIAS)
            float* __restrict__ out) {
    constexpr int NCQ = C / 4;       // 32 (C=128) or 16 (C=64)
    constexpr int NRG = 256 / NCQ;   // 8 or 16
    constexpr int R   = 64 / NRG;    // 8 or 4 rows per thread
    constexpr int RP  = R / 2;       // row pairs
    __shared__ float s_a[128 * SAS]; // [k][row], 34.8KB

    int tid  = threadIdx.x;
    int row0 = blockIdx.x * 64;
    int cq   = tid % NCQ;
    int rg   = tid / NCQ;

    ull acc[RP][4];
#pragma unroll
    for (int rp = 0; rp < RP; rp++)
#pragma unroll
        for (int c = 0; c < 4; c++) acc[rp][c] = 0ULL;

    const float* As[4] = {A0, A1, A2, A3};
#pragma unroll 1
    for (int g = 0; g < G; g++) {
        __syncthreads();
        const float* A = As[g];
        int srow = tid & 63;
        int kb   = (tid >> 6) * 32;
        int grow = row0 + srow;
#pragma unroll
        for (int q = 0; q < 8; q++) {
            float4 v = (grow < Nn) ? *(const float4*)(A + (size_t)grow * 128 + kb + q * 4)
                                   : make_float4(0.f, 0.f, 0.f, 0.f);
            s_a[(kb + q * 4 + 0) * SAS + srow] = v.x;
            s_a[(kb + q * 4 + 1) * SAS + srow] = v.y;
            s_a[(kb + q * 4 + 2) * SAS + srow] = v.z;
            s_a[(kb + q * 4 + 3) * SAS + srow] = v.w;
        }
        __syncthreads();

        const float* Wg = W + (size_t)g * 128 * C;
#pragma unroll 8
        for (int k = 0; k < 128; k++) {
            float4 w = __ldg((const float4*)(Wg + (size_t)k * C) + cq);
            ull wp0 = pk2(w.x), wp1 = pk2(w.y), wp2 = pk2(w.z), wp3 = pk2(w.w);
            const float* ab = &s_a[k * SAS + rg * R];
            if (RP == 4) {
                ulonglong2 a01 = *(const ulonglong2*)ab;
                ulonglong2 a23 = *(const ulonglong2*)(ab + 4);   // FIXED: rows +4..+7
                ull ap[4] = { a01.x, a01.y, a23.x, a23.y };
#pragma unroll
                for (int rp = 0; rp < 4; rp++) {
                    acc[rp][0] = fma2(ap[rp], wp0, acc[rp][0]);
                    acc[rp][1] = fma2(ap[rp], wp1, acc[rp][1]);
                    acc[rp][2] = fma2(ap[rp], wp2, acc[rp][2]);
                    acc[rp][3] = fma2(ap[rp], wp3, acc[rp][3]);
                }
            } else {
                ulonglong2 a01 = *(const ulonglong2*)ab;
                ull ap[2] = { a01.x, a01.y };
#pragma unroll
                for (int rp = 0; rp < 2; rp++) {
                    acc[rp][0] = fma2(ap[rp], wp0, acc[rp][0]);
                    acc[rp][1] = fma2(ap[rp], wp1, acc[rp][1]);
                    acc[rp][2] = fma2(ap[rp], wp2, acc[rp][2]);
                    acc[rp][3] = fma2(ap[rp], wp3, acc[rp][3]);
                }
            }
        }
    }

    float4 bv = BIAS ? *(const float4*)(bias + cq * 4) : make_float4(0.f, 0.f, 0.f, 0.f);
#pragma unroll
    for (int rp = 0; rp < RP; rp++) {
        float2 c0 = up2(acc[rp][0]), c1 = up2(acc[rp][1]);
        float2 c2 = up2(acc[rp][2]), c3 = up2(acc[rp][3]);
        int r0 = row0 + rg * R + rp * 2;
        float4 o0 = make_float4(c0.x + bv.x, c1.x + bv.y, c2.x + bv.z, c3.x + bv.w);
        float4 o1 = make_float4(c0.y + bv.x, c1.y + bv.y, c2.y + bv.z, c3.y + bv.w);
        if (RELU) {
            o0.x = fmaxf(o0.x, 0.f); o0.y = fmaxf(o0.y, 0.f);
            o0.z = fmaxf(o0.z, 0.f); o0.w = fmaxf(o0.w, 0.f);
            o1.x = fmaxf(o1.x, 0.f); o1.y = fmaxf(o1.y, 0.f);
            o1.z = fmaxf(o1.z, 0.f); o1.w = fmaxf(o1.w, 0.f);
        }
        if (r0 < Nn)     *(float4*)(out + (size_t)r0 * C + cq * 4)       = o0;
        if (r0 + 1 < Nn) *(float4*)(out + (size_t)(r0 + 1) * C + cq * 4) = o1;
    }
}

// ---------------- edge kernel ----------------
// hidden[e] = relu(P[i_e] + Q[j_e] + ea_e*W1c + b1); msg = hidden*W2 + b2 -> atomic
#define ST 132
#define EDGE_SMEM_BYTES ((128 * ST + 3 * 16 * ST) * 4 + 256 * 4)

__global__ void __launch_bounds__(256, 2)
edge_kernel(const float* __restrict__ P, const float* __restrict__ Q,
            const int* __restrict__ row, const int* __restrict__ col,
            const float* __restrict__ ea,
            const float* __restrict__ W1c,   // W1 + 256*128, [16][128]
            const float* __restrict__ b1,
            const float* __restrict__ W2, const float* __restrict__ b2,
            float* __restrict__ hout) {
    extern __shared__ float smf[];
    float* sHT = smf;                 // [128 col][ST] hidden^T
    float* sB  = sHT + 128 * ST;      // [16 k][ST]    W2 chunk
    float* sEA = sB  + 16 * ST;       // [16 k][ST]    ea^T (edge contiguous)
    float* sWc = sEA + 16 * ST;       // [16 k][ST]    W1c
    int* sCI   = (int*)(sWc + 16 * ST);
    int* sCJ   = sCI + 128;

    const int tid = threadIdx.x;
    const int tx  = tid & 15;         // col group: cols tx*8..+7
    const int ty  = tid >> 4;         // edge group: edges ty*8..+7
    const int e0  = blockIdx.x * 128; // Ee % 128 == 0
    const int wk  = tid >> 5;         // W2-stage row within half-tile
    const int wc  = (tid & 31) * 4;   // W2-stage col

    if (tid < 128) { sCI[tid] = col[e0 + tid]; sCJ[tid] = row[e0 + tid]; }
    {   // stage ea transposed
        int er = tid >> 1, hh = tid & 1;
        const float* eb = ea + (size_t)(e0 + er) * 16 + hh * 8;
        float4 v0 = *(const float4*)eb;
        float4 v1 = *(const float4*)(eb + 4);
        sEA[(hh * 8 + 0) * ST + er] = v0.x;
        sEA[(hh * 8 + 1) * ST + er] = v0.y;
        sEA[(hh * 8 + 2) * ST + er] = v0.z;
        sEA[(hh * 8 + 3) * ST + er] = v0.w;
        sEA[(hh * 8 + 4) * ST + er] = v1.x;
        sEA[(hh * 8 + 5) * ST + er] = v1.y;
        sEA[(hh * 8 + 6) * ST + er] = v1.z;
        sEA[(hh * 8 + 7) * ST + er] = v1.w;
    }
    {   // stage W1c
        int k = tid >> 4, c = (tid & 15) * 8;
        *(float4*)&sWc[k * ST + c]     = *(const float4*)(W1c + (size_t)k * 128 + c);
        *(float4*)&sWc[k * ST + c + 4] = *(const float4*)(W1c + (size_t)k * 128 + c + 4);
    }
    __syncthreads();

    ull acc[8][4];
#pragma unroll
    for (int r = 0; r < 8; r++)
#pragma unroll
        for (int p = 0; p < 4; p++) acc[r][p] = 0ULL;

    // ---------- ea * W1c (K=16) ----------
#pragma unroll
    for (int k = 0; k < 16; k++) {
        ulonglong2 bx = *(const ulonglong2*)&sWc[k * ST + tx * 8];
        ulonglong2 by = *(const ulonglong2*)&sWc[k * ST + tx * 8 + 4];
#pragma unroll
        for (int r = 0; r < 8; r++) {
            ull a = pk2(sEA[k * ST + ty * 8 + r]);
            acc[r][0] = fma2(a, bx.x, acc[r][0]);
            acc[r][1] = fma2(a, bx.y, acc[r][1]);
            acc[r][2] = fma2(a, by.x, acc[r][2]);
            acc[r][3] = fma2(a, by.y, acc[r][3]);
        }
    }

    // ---------- + P[i] + Q[j] + b1, relu (repack into acc) ----------
    {
        float4 bv0 = *(const float4*)(b1 + tx * 8);
        float4 bv1 = *(const float4*)(b1 + tx * 8 + 4);
#pragma unroll
        for (int r = 0; r < 8; r++) {
            int i = sCI[ty * 8 + r];
            int j = sCJ[ty * 8 + r];
            const float4* pp = (const float4*)(P + (size_t)i * 128 + tx * 8);
            const float4* qq = (const float4*)(Q + (size_t)j * 128 + tx * 8);
            float4 p0 = pp[0], p1 = pp[1];
            float4 q0 = qq[0], q1 = qq[1];
            float2 v0 = up2(acc[r][0]), v1 = up2(acc[r][1]);
            float2 v2 = up2(acc[r][2]), v3 = up2(acc[r][3]);
            v0.x = fmaxf(v0.x + p0.x + q0.x + bv0.x, 0.f);
            v0.y = fmaxf(v0.y + p0.y + q0.y + bv0.y, 0.f);
            v1.x = fmaxf(v1.x + p0.z + q0.z + bv0.z, 0.f);
            v1.y = fmaxf(v1.y + p0.w + q0.w + bv0.w, 0.f);
            v2.x = fmaxf(v2.x + p1.x + q1.x + bv1.x, 0.f);
            v2.y = fmaxf(v2.y + p1.y + q1.y + bv1.y, 0.f);
            v3.x = fmaxf(v3.x + p1.z + q1.z + bv1.z, 0.f);
            v3.y = fmaxf(v3.y + p1.w + q1.w + bv1.w, 0.f);
            acc[r][0] = pack2(v0.x, v0.y);
            acc[r][1] = pack2(v1.x, v1.y);
            acc[r][2] = pack2(v2.x, v2.y);
            acc[r][3] = pack2(v3.x, v3.y);
        }
    }

    // ---------- store hidden^T into sHT ----------
#pragma unroll
    for (int p = 0; p < 4; p++) {
        float2 v[8];
#pragma unroll
        for (int r = 0; r < 8; r++) v[r] = up2(acc[r][p]);
        int c0 = tx * 8 + 2 * p;
        *(float4*)&sHT[c0 * ST + ty * 8]           = make_float4(v[0].x, v[1].x, v[2].x, v[3].x);
        *(float4*)&sHT[c0 * ST + ty * 8 + 4]       = make_float4(v[4].x, v[5].x, v[6].x, v[7].x);
        *(float4*)&sHT[(c0 + 1) * ST + ty * 8]     = make_float4(v[0].y, v[1].y, v[2].y, v[3].y);
        *(float4*)&sHT[(c0 + 1) * ST + ty * 8 + 4] = make_float4(v[4].y, v[5].y, v[6].y, v[7].y);
    }

    // ---------- msg = hidden * W2 (K=128, 8 chunks) ----------
#pragma unroll
    for (int r = 0; r < 8; r++)
#pragma unroll
        for (int p = 0; p < 4; p++) acc[r][p] = 0ULL;

#pragma unroll 1
    for (int c = 0; c < 8; c++) {
        float4 w0 = *(const float4*)(W2 + (size_t)(c * 16 + wk) * 128 + wc);
        float4 w1 = *(const float4*)(W2 + (size_t)(c * 16 + 8 + wk) * 128 + wc);
        __syncthreads();   // sB consumed; (c==0) also orders sHT stores
        *(float4*)&sB[wk * ST + wc]       = w0;
        *(float4*)&sB[(wk + 8) * ST + wc] = w1;
        __syncthreads();
#pragma unroll
        for (int kk = 0; kk < 16; kk++) {
            int k = c * 16 + kk;
            float4 a0 = *(const float4*)&sHT[k * ST + ty * 8];
            float4 a1 = *(const float4*)&sHT[k * ST + ty * 8 + 4];
            ulonglong2 bx = *(const ulonglong2*)&sB[kk * ST + tx * 8];
            ulonglong2 by = *(const ulonglong2*)&sB[kk * ST + tx * 8 + 4];
            ull aa[8] = { pk2(a0.x), pk2(a0.y), pk2(a0.z), pk2(a0.w),
                          pk2(a1.x), pk2(a1.y), pk2(a1.z), pk2(a1.w) };
#pragma unroll
            for (int r = 0; r < 8; r++) {
                acc[r][0] = fma2(aa[r], bx.x, acc[r][0]);
                acc[r][1] = fma2(aa[r], bx.y, acc[r][1]);
                acc[r][2] = fma2(aa[r], by.x, acc[r][2]);
                acc[r][3] = fma2(aa[r], by.y, acc[r][3]);
            }
        }
    }

    // ---------- + b2, atomic scatter ----------
    {
        float bv[8];
#pragma unroll
        for (int j = 0; j < 8; j++) bv[j] = b2[tx * 8 + j];
#pragma unroll
        for (int r = 0; r < 8; r++) {
            int tgt = sCI[ty * 8 + r];
            float* hp = hout + (size_t)tgt * 128 + tx * 8;
#pragma unroll
            for (int p = 0; p < 4; p++) {
                float2 v = up2(acc[r][p]);
                atomicAdd(hp + 2 * p,     v.x + bv[2 * p]);
                atomicAdd(hp + 2 * p + 1, v.y + bv[2 * p + 1]);
            }
        }
    }
}

// ---------------- SpMM: out_i = sum_e w_e * vin[src_e], CSR, warp per node ----------------
__global__ void __launch_bounds__(128)
spmm_kernel(const float* __restrict__ vin, float* __restrict__ vout) {
    int node = (blockIdx.x * blockDim.x + threadIdx.x) >> 5;
    int lane = threadIdx.x & 31;
    if (node >= Nn) return;
    int s = g_off[node], e = g_off[node + 1];
    float4 acc = make_float4(0.f, 0.f, 0.f, 0.f);
    int idx = s;
    for (; idx + 1 < e; idx += 2) {
        int   j0 = g_src[idx],     j1 = g_src[idx + 1];
        float w0 = g_wgt[idx],     w1 = g_wgt[idx + 1];
        float4 v0 = ((const float4*)(vin + (size_t)j0 * 128))[lane];
        float4 v1 = ((const float4*)(vin + (size_t)j1 * 128))[lane];
        acc.x = fmaf(w0, v0.x, acc.x); acc.y = fmaf(w0, v0.y, acc.y);
        acc.z = fmaf(w0, v0.z, acc.z); acc.w = fmaf(w0, v0.w, acc.w);
        acc.x = fmaf(w1, v1.x, acc.x); acc.y = fmaf(w1, v1.y, acc.y);
        acc.z = fmaf(w1, v1.z, acc.z); acc.w = fmaf(w1, v1.w, acc.w);
    }
    if (idx < e) {
        int   j0 = g_src[idx];
        float w0 = g_wgt[idx];
        float4 v0 = ((const float4*)(vin + (size_t)j0 * 128))[lane];
        acc.x = fmaf(w0, v0.x, acc.x); acc.y = fmaf(w0, v0.y, acc.y);
        acc.z = fmaf(w0, v0.z, acc.z); acc.w = fmaf(w0, v0.w, acc.w);
    }
    ((float4*)(vout + (size_t)node * 128))[lane] = acc;
}

// ---------------- launch ----------------
extern "C" void kernel_launch(void* const* d_in, const int* in_sizes, int n_in,
                              void* d_out, int out_size) {
    const float* x   = (const float*)d_in[0];
    const int*   ei  = (const int*)  d_in[1];
    const float* ea  = (const float*)d_in[2];
    const float* W1  = (const float*)d_in[3];
    const float* b1  = (const float*)d_in[4];
    const float* W2  = (const float*)d_in[5];
    const float* b2  = (const float*)d_in[6];
    const float* t0W = (const float*)d_in[7];
    const float* t0b = (const float*)d_in[8];
    const float* t1W = (const float*)d_in[9];
    const float* t1b = (const float*)d_in[10];
    const float* t2W = (const float*)d_in[11];
    const float* t2b = (const float*)d_in[12];
    const int* row = ei;        // source j
    const int* col = ei + Ee;   // target i

    float *ph, *pa, *pp1, *pp2, *pp3;
    cudaGetSymbolAddress((void**)&ph,  g_h);
    cudaGetSymbolAddress((void**)&pa,  g_a);
    cudaGetSymbolAddress((void**)&pp1, g_p1);
    cudaGetSymbolAddress((void**)&pp2, g_p2);
    cudaGetSymbolAddress((void**)&pp3, g_p3);

    cudaFuncSetAttribute(edge_kernel,
                         cudaFuncAttributeMaxDynamicSharedMemorySize,
                         EDGE_SMEM_BYTES);

    const int GEMM_GRID = (Nn + 63) / 64;

    // 1..3: init, P = x*W1a, Q = x*W1b; 4: edge kernel (ncu slot)
    init_kernel<<<4096, 256>>>();
    gemm_kernel<1, 128, 0, 0><<<GEMM_GRID, 256>>>(x, x, x, x, W1,             nullptr, pp1);
    gemm_kernel<1, 128, 0, 0><<<GEMM_GRID, 256>>>(x, x, x, x, W1 + 128 * 128, nullptr, pp2);
    edge_kernel<<<Ee / 128, 256, EDGE_SMEM_BYTES>>>(pp1, pp2, row, col, ea,
                                                    W1 + 256 * 128, b1, W2, b2, ph);

    // CSR prep (not needed until spmm)
    count_kernel<<<Ee / 256, 256>>>(col);
    scan_kernel<<<1, 1024>>>();
    dis_kernel<<<(Nn + 255) / 256, 256>>>();
    scatter_kernel<<<Ee / 256, 256>>>(row, col);

    const int SPMM_GRID = (Nn + 3) / 4;

    // layer 0: h -> a  (ReLU)
    spmm_kernel<<<SPMM_GRID, 128>>>(ph,  pp1);
    spmm_kernel<<<SPMM_GRID, 128>>>(pp1, pp2);
    spmm_kernel<<<SPMM_GRID, 128>>>(pp2, pp3);
    gemm_kernel<4, 128, 1, 1><<<GEMM_GRID, 256>>>(ph, pp1, pp2, pp3, t0W, t0b, pa);

    // layer 1: a -> h  (ReLU)
    spmm_kernel<<<SPMM_GRID, 128>>>(pa,  pp1);
    spmm_kernel<<<SPMM_GRID, 128>>>(pp1, pp2);
    spmm_kernel<<<SPMM_GRID, 128>>>(pp2, pp3);
    gemm_kernel<4, 128, 1, 1><<<GEMM_GRID, 256>>>(pa, pp1, pp2, pp3, t1W, t1b, ph);

    // layer 2: h -> out (no ReLU, C=64)
    spmm_kernel<<<SPMM_GRID, 128>>>(ph,  pp1);
    spmm_kernel<<<SPMM_GRID, 128>>>(pp1, pp2);
    spmm_kernel<<<SPMM_GRID, 128>>>(pp2, pp3);
    gemm_kernel<4, 64, 0, 1><<<GEMM_GRID, 256>>>(ph, pp1, pp2, pp3, t2W, t2b, (float*)d_out);
}

// round 6
// speedup vs baseline: 15.4906x; 1.6629x over previous
#include <cuda_runtime.h>
#include <math.h>

typedef unsigned long long ull;

#define Nn   50000
#define Ee   800000
#define Hd   128
#define OUTC 64

// ---------------- scratch (static device memory; no allocations) ----------------
__device__ float g_h [Nn * Hd];
__device__ float g_a [Nn * Hd];
__device__ float g_p1[Nn * Hd];   // P = x*W1a + b1 (before spmm stage)
__device__ float g_p2[Nn * Hd];   // Q = x*W1b
__device__ float g_p3[Nn * Hd];   // S = aggregated hidden
__device__ float g_dis[Nn];
__device__ float g_degf[Nn];
__device__ int   g_cnt[Nn];
__device__ int   g_cur[Nn];
__device__ int   g_off[Nn + 1];
__device__ int   g_src[Ee];
__device__ int   g_eid[Ee];
__device__ float g_wgt[Ee];

// ---------------- packed f32x2 helpers ----------------
__device__ __forceinline__ ull pk2(float a) {
    ull d; unsigned int u = __float_as_uint(a);
    asm("mov.b64 %0, {%1, %1};" : "=l"(d) : "r"(u));
    return d;
}
__device__ __forceinline__ ull fma2(ull a, ull b, ull c) {
    ull d;
    asm("fma.rn.f32x2 %0, %1, %2, %3;" : "=l"(d) : "l"(a), "l"(b), "l"(c));
    return d;
}
__device__ __forceinline__ float2 up2(ull v) {
    unsigned int lo, hi;
    asm("mov.b64 {%0, %1}, %2;" : "=r"(lo), "=r"(hi) : "l"(v));
    return make_float2(__uint_as_float(lo), __uint_as_float(hi));
}

// ---------------- setup kernels ----------------
__global__ void init_kernel() {
    int i = blockIdx.x * blockDim.x + threadIdx.x;
    if (i < Nn) { g_cnt[i] = 0; g_cur[i] = 0; }
}

__global__ void count_kernel(const int* __restrict__ col) {
    int e = blockIdx.x * blockDim.x + threadIdx.x;
    if (e < Ee) atomicAdd(&g_cnt[col[e]], 1);
}

// exclusive scan of g_cnt -> g_off; also dis = rsqrt(deg), degf = (float)deg
__global__ void scan_dis_kernel() {
    __shared__ int sm[1024];
    __shared__ int carry;
    int tid = threadIdx.x;
    if (tid == 0) { carry = 0; g_off[0] = 0; }
    __syncthreads();
    for (int base = 0; base < Nn; base += 1024) {
        int i = base + tid;
        int v = (i < Nn) ? g_cnt[i] : 0;
        sm[tid] = v;
        __syncthreads();
        for (int s = 1; s < 1024; s <<= 1) {
            int t = (tid >= s) ? sm[tid - s] : 0;
            __syncthreads();
            sm[tid] += t;
            __syncthreads();
        }
        if (i < Nn) {
            g_off[i + 1] = carry + sm[tid];
            g_dis[i]  = (v > 0) ? rsqrtf((float)v) : 0.0f;
            g_degf[i] = (float)v;
        }
        __syncthreads();
        if (tid == 1023) carry += sm[1023];
        __syncthreads();
    }
}

__global__ void scatter_kernel(const int* __restrict__ row, const int* __restrict__ col) {
    int e = blockIdx.x * blockDim.x + threadIdx.x;
    if (e < Ee) {
        int i = col[e], j = row[e];
        int p = atomicAdd(&g_cur[i], 1);
        int o = g_off[i] + p;
        g_src[o] = j;
        g_eid[o] = e;
        g_wgt[o] = g_dis[i] * g_dis[j];
    }
}

// ---------------- generic dense GEMM: out = sum_{g<G} A_g W_g (+bias)(+relu) -----
// BMODE: 0 = none, 1 = +bias, 2 = +deg[row]*bias
#define SAS 68
template <int G, int C, int RELU, int BMODE>
__global__ void __launch_bounds__(256)
gemm_kernel(const float* __restrict__ A0, const float* __restrict__ A1,
            const float* __restrict__ A2, const float* __restrict__ A3,
            const float* __restrict__ W,     // [G][128][C]
            const float* __restrict__ bias,  // [C]
            const float* __restrict__ degf,  // [Nn] (BMODE==2)
            float* __restrict__ out) {
    constexpr int NCQ = C / 4;
    constexpr int NRG = 256 / NCQ;
    constexpr int R   = 64 / NRG;
    constexpr int RP  = R / 2;
    __shared__ float s_a[128 * SAS];

    int tid  = threadIdx.x;
    int row0 = blockIdx.x * 64;
    int cq   = tid % NCQ;
    int rg   = tid / NCQ;

    ull acc[RP][4];
#pragma unroll
    for (int rp = 0; rp < RP; rp++)
#pragma unroll
        for (int c = 0; c < 4; c++) acc[rp][c] = 0ULL;

    const float* As[4] = {A0, A1, A2, A3};
#pragma unroll 1
    for (int g = 0; g < G; g++) {
        __syncthreads();
        const float* A = As[g];
        int srow = tid & 63;
        int kb   = (tid >> 6) * 32;
        int grow = row0 + srow;
#pragma unroll
        for (int q = 0; q < 8; q++) {
            float4 v = (grow < Nn) ? *(const float4*)(A + (size_t)grow * 128 + kb + q * 4)
                                   : make_float4(0.f, 0.f, 0.f, 0.f);
            s_a[(kb + q * 4 + 0) * SAS + srow] = v.x;
            s_a[(kb + q * 4 + 1) * SAS + srow] = v.y;
            s_a[(kb + q * 4 + 2) * SAS + srow] = v.z;
            s_a[(kb + q * 4 + 3) * SAS + srow] = v.w;
        }
        __syncthreads();

        const float* Wg = W + (size_t)g * 128 * C;
#pragma unroll 8
        for (int k = 0; k < 128; k++) {
            float4 w = __ldg((const float4*)(Wg + (size_t)k * C) + cq);
            ull wp0 = pk2(w.x), wp1 = pk2(w.y), wp2 = pk2(w.z), wp3 = pk2(w.w);
            const float* ab = &s_a[k * SAS + rg * R];
            if (RP == 4) {
                ulonglong2 a01 = *(const ulonglong2*)ab;
                ulonglong2 a23 = *(const ulonglong2*)(ab + 4);
                ull ap[4] = { a01.x, a01.y, a23.x, a23.y };
#pragma unroll
                for (int rp = 0; rp < 4; rp++) {
                    acc[rp][0] = fma2(ap[rp], wp0, acc[rp][0]);
                    acc[rp][1] = fma2(ap[rp], wp1, acc[rp][1]);
                    acc[rp][2] = fma2(ap[rp], wp2, acc[rp][2]);
                    acc[rp][3] = fma2(ap[rp], wp3, acc[rp][3]);
                }
            } else {
                ulonglong2 a01 = *(const ulonglong2*)ab;
                ull ap[2] = { a01.x, a01.y };
#pragma unroll
                for (int rp = 0; rp < 2; rp++) {
                    acc[rp][0] = fma2(ap[rp], wp0, acc[rp][0]);
                    acc[rp][1] = fma2(ap[rp], wp1, acc[rp][1]);
                    acc[rp][2] = fma2(ap[rp], wp2, acc[rp][2]);
                    acc[rp][3] = fma2(ap[rp], wp3, acc[rp][3]);
                }
            }
        }
    }

    float4 bv = (BMODE > 0) ? *(const float4*)(bias + cq * 4)
                            : make_float4(0.f, 0.f, 0.f, 0.f);
#pragma unroll
    for (int rp = 0; rp < RP; rp++) {
        float2 c0 = up2(acc[rp][0]), c1 = up2(acc[rp][1]);
        float2 c2 = up2(acc[rp][2]), c3 = up2(acc[rp][3]);
        int r0 = row0 + rg * R + rp * 2;
        float d0 = 1.f, d1 = 1.f;
        if (BMODE == 2) {
            d0 = (r0 < Nn)     ? degf[r0]     : 0.f;
            d1 = (r0 + 1 < Nn) ? degf[r0 + 1] : 0.f;
        }
        float4 o0 = make_float4(c0.x + d0 * bv.x, c1.x + d0 * bv.y,
                                c2.x + d0 * bv.z, c3.x + d0 * bv.w);
        float4 o1 = make_float4(c0.y + d1 * bv.x, c1.y + d1 * bv.y,
                                c2.y + d1 * bv.z, c3.y + d1 * bv.w);
        if (RELU) {
            o0.x = fmaxf(o0.x, 0.f); o0.y = fmaxf(o0.y, 0.f);
            o0.z = fmaxf(o0.z, 0.f); o0.w = fmaxf(o0.w, 0.f);
            o1.x = fmaxf(o1.x, 0.f); o1.y = fmaxf(o1.y, 0.f);
            o1.z = fmaxf(o1.z, 0.f); o1.w = fmaxf(o1.w, 0.f);
        }
        if (r0 < Nn)     *(float4*)(out + (size_t)r0 * C + cq * 4)       = o0;
        if (r0 + 1 < Nn) *(float4*)(out + (size_t)(r0 + 1) * C + cq * 4) = o1;
    }
}

// ---------------- agg kernel: S_i = sum_{e in CSR[i]} relu(P_i + Q_{j_e} + ea_e*W1c) ----
// warp per target node; lane owns 4 columns. P already includes b1.
__global__ void __launch_bounds__(256)
agg_kernel(const float* __restrict__ P, const float* __restrict__ Q,
           const float* __restrict__ ea,
           const float* __restrict__ W1c,   // [16][128]
           float* __restrict__ S) {
    int i    = (blockIdx.x * blockDim.x + threadIdx.x) >> 5;
    int lane = threadIdx.x & 31;
    if (i >= Nn) return;

    float4 w1c[16];
#pragma unroll
    for (int k = 0; k < 16; k++)
        w1c[k] = __ldg((const float4*)(W1c + (size_t)k * 128) + lane);

    float4 p = *(const float4*)(P + (size_t)i * 128 + lane * 4);
    float4 acc = make_float4(0.f, 0.f, 0.f, 0.f);

    int s = g_off[i], e = g_off[i + 1];
#pragma unroll 2
    for (int t = s; t < e; t++) {
        int j   = g_src[t];
        int eid = g_eid[t];
        const float4* eb = (const float4*)(ea + (size_t)eid * 16);
        float4 e0 = __ldg(eb + 0), e1 = __ldg(eb + 1);
        float4 e2 = __ldg(eb + 2), e3 = __ldg(eb + 3);
        float4 q = __ldg((const float4*)(Q + (size_t)j * 128) + lane);
        float4 c;
        c.x = p.x + q.x; c.y = p.y + q.y; c.z = p.z + q.z; c.w = p.w + q.w;
        const float ks[16] = { e0.x, e0.y, e0.z, e0.w, e1.x, e1.y, e1.z, e1.w,
                               e2.x, e2.y, e2.z, e2.w, e3.x, e3.y, e3.z, e3.w };
#pragma unroll
        for (int k = 0; k < 16; k++) {
            c.x = fmaf(ks[k], w1c[k].x, c.x);
            c.y = fmaf(ks[k], w1c[k].y, c.y);
            c.z = fmaf(ks[k], w1c[k].z, c.z);
            c.w = fmaf(ks[k], w1c[k].w, c.w);
        }
        acc.x += fmaxf(c.x, 0.f);
        acc.y += fmaxf(c.y, 0.f);
        acc.z += fmaxf(c.z, 0.f);
        acc.w += fmaxf(c.w, 0.f);
    }
    *(float4*)(S + (size_t)i * 128 + lane * 4) = acc;
}

// ---------------- SpMM: out_i = sum_e w_e * vin[src_e], CSR, warp per node ----------------
__global__ void __launch_bounds__(128)
spmm_kernel(const float* __restrict__ vin, float* __restrict__ vout) {
    int node = (blockIdx.x * blockDim.x + threadIdx.x) >> 5;
    int lane = threadIdx.x & 31;
    if (node >= Nn) return;
    int s = g_off[node], e = g_off[node + 1];
    float4 acc = make_float4(0.f, 0.f, 0.f, 0.f);
    int idx = s;
    for (; idx + 1 < e; idx += 2) {
        int   j0 = g_src[idx],     j1 = g_src[idx + 1];
        float w0 = g_wgt[idx],     w1 = g_wgt[idx + 1];
        float4 v0 = ((const float4*)(vin + (size_t)j0 * 128))[lane];
        float4 v1 = ((const float4*)(vin + (size_t)j1 * 128))[lane];
        acc.x = fmaf(w0, v0.x, acc.x); acc.y = fmaf(w0, v0.y, acc.y);
        acc.z = fmaf(w0, v0.z, acc.z); acc.w = fmaf(w0, v0.w, acc.w);
        acc.x = fmaf(w1, v1.x, acc.x); acc.y = fmaf(w1, v1.y, acc.y);
        acc.z = fmaf(w1, v1.z, acc.z); acc.w = fmaf(w1, v1.w, acc.w);
    }
    if (idx < e) {
        int   j0 = g_src[idx];
        float w0 = g_wgt[idx];
        float4 v0 = ((const float4*)(vin + (size_t)j0 * 128))[lane];
        acc.x = fmaf(w0, v0.x, acc.x); acc.y = fmaf(w0, v0.y, acc.y);
        acc.z = fmaf(w0, v0.z, acc.z); acc.w = fmaf(w0, v0.w, acc.w);
    }
    ((float4*)(vout + (size_t)node * 128))[lane] = acc;
}

// ---------------- launch ----------------
extern "C" void kernel_launch(void* const* d_in, const int* in_sizes, int n_in,
                              void* d_out, int out_size) {
    const float* x   = (const float*)d_in[0];
    const int*   ei  = (const int*)  d_in[1];
    const float* ea  = (const float*)d_in[2];
    const float* W1  = (const float*)d_in[3];
    const float* b1  = (const float*)d_in[4];
    const float* W2  = (const float*)d_in[5];
    const float* b2  = (const float*)d_in[6];
    const float* t0W = (const float*)d_in[7];
    const float* t0b = (const float*)d_in[8];
    const float* t1W = (const float*)d_in[9];
    const float* t1b = (const float*)d_in[10];
    const float* t2W = (const float*)d_in[11];
    const float* t2b = (const float*)d_in[12];
    const int* row = ei;        // source j
    const int* col = ei + Ee;   // target i

    float *ph, *pa, *pp1, *pp2, *pp3, *pdeg;
    cudaGetSymbolAddress((void**)&ph,   g_h);
    cudaGetSymbolAddress((void**)&pa,   g_a);
    cudaGetSymbolAddress((void**)&pp1,  g_p1);
    cudaGetSymbolAddress((void**)&pp2,  g_p2);
    cudaGetSymbolAddress((void**)&pp3,  g_p3);
    cudaGetSymbolAddress((void**)&pdeg, g_degf);

    const int GEMM_GRID = (Nn + 63) / 64;
    const int WARP_GRID = (Nn * 32 + 255) / 256;

    // CSR prep
    init_kernel<<<(Nn + 255) / 256, 256>>>();
    count_kernel<<<Ee / 256, 256>>>(col);
    scan_dis_kernel<<<1, 1024>>>();
    // P = x*W1a + b1 (4th launch -> ncu slot), Q = x*W1b
    gemm_kernel<1, 128, 0, 1><<<GEMM_GRID, 256>>>(x, x, x, x, W1,             b1,      nullptr, pp1);
    gemm_kernel<1, 128, 0, 0><<<GEMM_GRID, 256>>>(x, x, x, x, W1 + 128 * 128, nullptr, nullptr, pp2);
    scatter_kernel<<<Ee / 256, 256>>>(row, col);

    // S = per-target aggregated hidden; h = S*W2 + deg*b2
    agg_kernel<<<WARP_GRID, 256>>>(pp1, pp2, ea, W1 + 256 * 128, pp3);
    gemm_kernel<1, 128, 0, 2><<<GEMM_GRID, 256>>>(pp3, pp3, pp3, pp3, W2, b2, pdeg, ph);

    const int SPMM_GRID = (Nn + 3) / 4;

    // layer 0: h -> a  (ReLU)
    spmm_kernel<<<SPMM_GRID, 128>>>(ph,  pp1);
    spmm_kernel<<<SPMM_GRID, 128>>>(pp1, pp2);
    spmm_kernel<<<SPMM_GRID, 128>>>(pp2, pp3);
    gemm_kernel<4, 128, 1, 1><<<GEMM_GRID, 256>>>(ph, pp1, pp2, pp3, t0W, t0b, nullptr, pa);

    // layer 1: a -> h  (ReLU)
    spmm_kernel<<<SPMM_GRID, 128>>>(pa,  pp1);
    spmm_kernel<<<SPMM_GRID, 128>>>(pp1, pp2);
    spmm_kernel<<<SPMM_GRID, 128>>>(pp2, pp3);
    gemm_kernel<4, 128, 1, 1><<<GEMM_GRID, 256>>>(pa, pp1, pp2, pp3, t1W, t1b, nullptr, ph);

    // layer 2: h -> out (no ReLU, C=64)
    spmm_kernel<<<SPMM_GRID, 128>>>(ph,  pp1);
    spmm_kernel<<<SPMM_GRID, 128>>>(pp1, pp2);
    spmm_kernel<<<SPMM_GRID, 128>>>(pp2, pp3);
    gemm_kernel<4, 64, 0, 1><<<GEMM_GRID, 256>>>(ph, pp1, pp2, pp3, t2W, t2b, nullptr, (float*)d_out);
}

// round 8
// speedup vs baseline: 18.7406x; 1.2098x over previous
#include <cuda_runtime.h>
#include <cuda_bf16.h>
#include <math.h>

typedef unsigned long long ull;

#define Nn   50000
#define Ee   800000

// ---------------- scratch (static device memory; no allocations) ----------------
__device__ float g_h [Nn * 128];
__device__ float g_a [Nn * 128];
__device__ float g_p1[Nn * 128];   // P = x*W1a + b1 (before spmm stage)
__device__ float g_p2[Nn * 128];   // Q = x*W1b
__device__ float g_p3[Nn * 128];   // S = aggregated hidden
__device__ float g_dis[Nn];
__device__ float g_degf[Nn];
__device__ int   g_cnt[Nn];
__device__ int   g_cur[Nn];
__device__ int   g_off[Nn + 1];
__device__ int   g_src[Ee];
__device__ int   g_eid[Ee];
__device__ float g_wgt[Ee];

// bf16 hi/lo weight fragment images (mma.sync per-thread order, SMEM-ready)
#define OFF_W1A 0
#define OFF_W1B 65536
#define OFF_W2  131072
#define OFF_T0  196608
#define OFF_T1  458752
#define OFF_T2  720896
__device__ __align__(16) unsigned char g_wbf[851968];

// ---------------- setup kernels ----------------
__global__ void init_kernel() {
    int i = blockIdx.x * blockDim.x + threadIdx.x;
    if (i < Nn) { g_cnt[i] = 0; g_cur[i] = 0; }
}

__global__ void count_kernel(const int* __restrict__ col) {
    int e = blockIdx.x * blockDim.x + threadIdx.x;
    if (e < Ee) atomicAdd(&g_cnt[col[e]], 1);
}

__global__ void scan_dis_kernel() {
    __shared__ int sm[1024];
    __shared__ int carry;
    int tid = threadIdx.x;
    if (tid == 0) { carry = 0; g_off[0] = 0; }
    __syncthreads();
    for (int base = 0; base < Nn; base += 1024) {
        int i = base + tid;
        int v = (i < Nn) ? g_cnt[i] : 0;
        sm[tid] = v;
        __syncthreads();
        for (int s = 1; s < 1024; s <<= 1) {
            int t = (tid >= s) ? sm[tid - s] : 0;
            __syncthreads();
            sm[tid] += t;
            __syncthreads();
        }
        if (i < Nn) {
            g_off[i + 1] = carry + sm[tid];
            g_dis[i]  = (v > 0) ? rsqrtf((float)v) : 0.0f;
            g_degf[i] = (float)v;
        }
        __syncthreads();
        if (tid == 1023) carry += sm[1023];
        __syncthreads();
    }
}

__global__ void scatter_kernel(const int* __restrict__ row, const int* __restrict__ col) {
    int e = blockIdx.x * blockDim.x + threadIdx.x;
    if (e < Ee) {
        int i = col[e], j = row[e];
        int p = atomicAdd(&g_cur[i], 1);
        int o = g_off[i] + p;
        g_src[o] = j;
        g_eid[o] = e;
        g_wgt[o] = g_dis[i] * g_dis[j];
    }
}

// ---------------- weight prep: fp32 [K=128][C] -> bf16 hi/lo mma fragment images ----
// Fragment order for m16n8k16 B operand (col layout):
//   byte = ((kstep*NT + ntile)*32 + lane)*8 + reg*4 + (k&1)*2
//   lane = (n&7)*4 + ((k&7)>>1), reg = (k&15)>>3
__global__ void wprep_kernel(const float* __restrict__ W1, const float* __restrict__ W2,
                             const float* __restrict__ t0W, const float* __restrict__ t1W,
                             const float* __restrict__ t2W) {
    int idx = blockIdx.x * blockDim.x + threadIdx.x;
    const int total = 212992;
    if (idx >= total) return;
    const float* src; unsigned char* dst; int C, e;
    if (idx < 16384)       { src = W1;         dst = g_wbf + OFF_W1A; C = 128; e = idx; }
    else if (idx < 32768)  { src = W1 + 16384; dst = g_wbf + OFF_W1B; C = 128; e = idx - 16384; }
    else if (idx < 49152)  { src = W2;         dst = g_wbf + OFF_W2;  C = 128; e = idx - 32768; }
    else if (idx < 114688) { src = t0W;        dst = g_wbf + OFF_T0;  C = 128; e = idx - 49152; }
    else if (idx < 180224) { src = t1W;        dst = g_wbf + OFF_T1;  C = 128; e = idx - 114688; }
    else                   { src = t2W;        dst = g_wbf + OFF_T2;  C = 64;  e = idx - 180224; }
    int per = 128 * C;
    int g = e / per, r = e - g * per;
    int k = r / C, n = r - k * C;
    float v = src[(size_t)g * per + (size_t)k * C + n];
    __nv_bfloat16 hi = __float2bfloat16(v);
    __nv_bfloat16 lo = __float2bfloat16(v - __bfloat162float(hi));
    int TB = C * 256;                 // bytes per split tile
    int NT = C >> 3;
    int kstep = k >> 4, kin = k & 15, reg = kin >> 3, kb = kin & 7;
    int lane = (n & 7) * 4 + (kb >> 1);
    int off = (((kstep * NT + (n >> 3)) * 32 + lane) << 3) + reg * 4 + (kb & 1) * 2;
    *(__nv_bfloat16*)(dst + (size_t)g * 2 * TB + off)      = hi;
    *(__nv_bfloat16*)(dst + (size_t)g * 2 * TB + TB + off) = lo;
}

// ---------------- mma.sync helper ----------------
__device__ __forceinline__ void mma16816(float& c0, float& c1, float& c2, float& c3,
                                         unsigned a0, unsigned a1, unsigned a2, unsigned a3,
                                         unsigned b0, unsigned b1) {
    asm volatile(
        "mma.sync.aligned.m16n8k16.row.col.f32.bf16.bf16.f32 "
        "{%0,%1,%2,%3}, {%4,%5,%6,%7}, {%8,%9}, {%0,%1,%2,%3};"
        : "+f"(c0), "+f"(c1), "+f"(c2), "+f"(c3)
        : "r"(a0), "r"(a1), "r"(a2), "r"(a3), "r"(b0), "r"(b1));
}

// ---------------- tensor-core GEMM (mma.sync bf16 split) ----------------
// out[128tile, C] = sum_g A_g W_g (+bias variants). BMODE: 0 none, 1 +bias, 2 +deg*bias
#define AST 136                       // A smem stride in bf16 (272 B, conflict-free frags)
#define A_SPLIT_BYTES (128 * AST * 2) // 34816
template <int G, int C, int RELU, int BMODE>
__global__ void __launch_bounds__(256, 1)
tc_gemm(const float* __restrict__ A0, const float* __restrict__ A1,
        const float* __restrict__ A2, const float* __restrict__ A3,
        const unsigned char* __restrict__ Wt,  // [G][hi frag TB][lo frag TB]
        const float* __restrict__ bias, const float* __restrict__ degf,
        float* __restrict__ out) {
    extern __shared__ __align__(16) unsigned char sm[];
    __nv_bfloat16* Ah = (__nv_bfloat16*)sm;
    __nv_bfloat16* Al = (__nv_bfloat16*)(sm + A_SPLIT_BYTES);
    unsigned char* Bf = sm + 2 * A_SPLIT_BYTES;   // 69632

    constexpr int NT = C / 8;
    constexpr int TB = C * 256;
    const int tid = threadIdx.x, wid = tid >> 5, lane = tid & 31;
    const int row0 = blockIdx.x * 128;

    float acc[NT][4];
#pragma unroll
    for (int nt = 0; nt < NT; nt++)
#pragma unroll
        for (int c = 0; c < 4; c++) acc[nt][c] = 0.f;

    const float* As[4] = {A0, A1, A2, A3};
#pragma unroll 1
    for (int g = 0; g < G; g++) {
        if (g > 0) __syncthreads();
        // ---- convert A_g (128 rows x 128 k fp32) -> bf16 hi/lo row-major ----
        {
            int r  = tid >> 1;
            int kh = tid & 1;
            int grow = row0 + r;
            const float* src = As[g] + (size_t)grow * 128 + kh * 64;
            __nv_bfloat16* hp = Ah + r * AST + kh * 64;
            __nv_bfloat16* lp = Al + r * AST + kh * 64;
#pragma unroll
            for (int q = 0; q < 16; q++) {
                float4 v = (grow < Nn) ? *(const float4*)(src + q * 4)
                                       : make_float4(0.f, 0.f, 0.f, 0.f);
                __nv_bfloat16 hx = __float2bfloat16(v.x);
                __nv_bfloat16 hy = __float2bfloat16(v.y);
                __nv_bfloat16 hz = __float2bfloat16(v.z);
                __nv_bfloat16 hw = __float2bfloat16(v.w);
                __nv_bfloat162 h01; h01.x = hx; h01.y = hy;
                __nv_bfloat162 h23; h23.x = hz; h23.y = hw;
                __nv_bfloat162 l01, l23;
                l01.x = __float2bfloat16(v.x - __bfloat162float(hx));
                l01.y = __float2bfloat16(v.y - __bfloat162float(hy));
                l23.x = __float2bfloat16(v.z - __bfloat162float(hz));
                l23.y = __float2bfloat16(v.w - __bfloat162float(hw));
                *(__nv_bfloat162*)(hp + q * 4)     = h01;
                *(__nv_bfloat162*)(hp + q * 4 + 2) = h23;
                *(__nv_bfloat162*)(lp + q * 4)     = l01;
                *(__nv_bfloat162*)(lp + q * 4 + 2) = l23;
            }
        }
        // ---- copy B fragment images (hi+lo) ----
        {
            const float4* srcB = (const float4*)(Wt + (size_t)g * 2 * TB);
            float4* dstB = (float4*)Bf;
            constexpr int NV = 2 * TB / 16;
#pragma unroll 4
            for (int i = tid; i < NV; i += 256) dstB[i] = srcB[i];
        }
        __syncthreads();

        // ---- compute: warp owns rows wid*16..+15, all C columns ----
        const int m0 = wid * 16 + (lane >> 2);
        const int kq = (lane & 3) * 2;
#pragma unroll 1
        for (int ks = 0; ks < 8; ks++) {
            int k0 = ks * 16 + kq;
            unsigned aH0 = *(const unsigned*)(Ah + m0 * AST + k0);
            unsigned aH1 = *(const unsigned*)(Ah + (m0 + 8) * AST + k0);
            unsigned aH2 = *(const unsigned*)(Ah + m0 * AST + k0 + 8);
            unsigned aH3 = *(const unsigned*)(Ah + (m0 + 8) * AST + k0 + 8);
            unsigned aL0 = *(const unsigned*)(Al + m0 * AST + k0);
            unsigned aL1 = *(const unsigned*)(Al + (m0 + 8) * AST + k0);
            unsigned aL2 = *(const unsigned*)(Al + m0 * AST + k0 + 8);
            unsigned aL3 = *(const unsigned*)(Al + (m0 + 8) * AST + k0 + 8);
            const unsigned char* bbase = Bf + ((size_t)(ks * NT) * 32 + lane) * 8;
#pragma unroll
            for (int nt = 0; nt < NT; nt++) {
                uint2 bh = *(const uint2*)(bbase + nt * 256);
                uint2 bl = *(const uint2*)(bbase + nt * 256 + TB);
                mma16816(acc[nt][0], acc[nt][1], acc[nt][2], acc[nt][3],
                         aH0, aH1, aH2, aH3, bh.x, bh.y);
                mma16816(acc[nt][0], acc[nt][1], acc[nt][2], acc[nt][3],
                         aH0, aH1, aH2, aH3, bl.x, bl.y);
                mma16816(acc[nt][0], acc[nt][1], acc[nt][2], acc[nt][3],
                         aL0, aL1, aL2, aL3, bh.x, bh.y);
            }
        }
    }

    // ---- epilogue: bias / deg*bias / relu, store ----
    const int mA = row0 + wid * 16 + (lane >> 2);
    const int mB = mA + 8;
    float dgA = 1.f, dgB = 1.f;
    if (BMODE == 2) {
        dgA = (mA < Nn) ? degf[mA] : 0.f;
        dgB = (mB < Nn) ? degf[mB] : 0.f;
    }
#pragma unroll
    for (int nt = 0; nt < NT; nt++) {
        int n0 = nt * 8 + (lane & 3) * 2;
        float bx = 0.f, by = 0.f;
        if (BMODE > 0) {
            float2 bv = *(const float2*)(bias + n0);
            bx = bv.x; by = bv.y;
        }
        float o0 = acc[nt][0], o1 = acc[nt][1], o2 = acc[nt][2], o3 = acc[nt][3];
        if (BMODE == 1) { o0 += bx; o1 += by; o2 += bx; o3 += by; }
        if (BMODE == 2) { o0 += dgA * bx; o1 += dgA * by; o2 += dgB * bx; o3 += dgB * by; }
        if (RELU) {
            o0 = fmaxf(o0, 0.f); o1 = fmaxf(o1, 0.f);
            o2 = fmaxf(o2, 0.f); o3 = fmaxf(o3, 0.f);
        }
        if (mA < Nn) *(float2*)(out + (size_t)mA * C + n0) = make_float2(o0, o1);
        if (mB < Nn) *(float2*)(out + (size_t)mB * C + n0) = make_float2(o2, o3);
    }
}

// ---------------- agg kernel: S_i = sum_{e in CSR[i]} relu(P_i + Q_{j_e} + ea_e*W1c) ----
__global__ void __launch_bounds__(256)
agg_kernel(const float* __restrict__ P, const float* __restrict__ Q,
           const float* __restrict__ ea,
           const float* __restrict__ W1c,   // [16][128]
           float* __restrict__ S) {
    int i    = (blockIdx.x * blockDim.x + threadIdx.x) >> 5;
    int lane = threadIdx.x & 31;
    if (i >= Nn) return;

    float4 w1c[16];
#pragma unroll
    for (int k = 0; k < 16; k++)
        w1c[k] = __ldg((const float4*)(W1c + (size_t)k * 128) + lane);

    float4 p = *(const float4*)(P + (size_t)i * 128 + lane * 4);
    float4 acc = make_float4(0.f, 0.f, 0.f, 0.f);

    int s = g_off[i], e = g_off[i + 1];
#pragma unroll 2
    for (int t = s; t < e; t++) {
        int j   = g_src[t];
        int eid = g_eid[t];
        const float4* eb = (const float4*)(ea + (size_t)eid * 16);
        float4 e0 = __ldg(eb + 0), e1 = __ldg(eb + 1);
        float4 e2 = __ldg(eb + 2), e3 = __ldg(eb + 3);
        float4 q = __ldg((const float4*)(Q + (size_t)j * 128) + lane);
        float4 c;
        c.x = p.x + q.x; c.y = p.y + q.y; c.z = p.z + q.z; c.w = p.w + q.w;
        const float ks[16] = { e0.x, e0.y, e0.z, e0.w, e1.x, e1.y, e1.z, e1.w,
                               e2.x, e2.y, e2.z, e2.w, e3.x, e3.y, e3.z, e3.w };
#pragma unroll
        for (int k = 0; k < 16; k++) {
            c.x = fmaf(ks[k], w1c[k].x, c.x);
            c.y = fmaf(ks[k], w1c[k].y, c.y);
            c.z = fmaf(ks[k], w1c[k].z, c.z);
            c.w = fmaf(ks[k], w1c[k].w, c.w);
        }
        acc.x += fmaxf(c.x, 0.f);
        acc.y += fmaxf(c.y, 0.f);
        acc.z += fmaxf(c.z, 0.f);
        acc.w += fmaxf(c.w, 0.f);
    }
    *(float4*)(S + (size_t)i * 128 + lane * 4) = acc;
}

// ---------------- SpMM: out_i = sum_e w_e * vin[src_e], CSR, warp per node ----------------
__global__ void __launch_bounds__(128)
spmm_kernel(const float* __restrict__ vin, float* __restrict__ vout) {
    int node = (blockIdx.x * blockDim.x + threadIdx.x) >> 5;
    int lane = threadIdx.x & 31;
    if (node >= Nn) return;
    int s = g_off[node], e = g_off[node + 1];
    float4 acc = make_float4(0.f, 0.f, 0.f, 0.f);
    int idx = s;
    for (; idx + 1 < e; idx += 2) {
        int   j0 = g_src[idx],     j1 = g_src[idx + 1];
        float w0 = g_wgt[idx],     w1 = g_wgt[idx + 1];
        float4 v0 = ((const float4*)(vin + (size_t)j0 * 128))[lane];
        float4 v1 = ((const float4*)(vin + (size_t)j1 * 128))[lane];
        acc.x = fmaf(w0, v0.x, acc.x); acc.y = fmaf(w0, v0.y, acc.y);
        acc.z = fmaf(w0, v0.z, acc.z); acc.w = fmaf(w0, v0.w, acc.w);
        acc.x = fmaf(w1, v1.x, acc.x); acc.y = fmaf(w1, v1.y, acc.y);
        acc.z = fmaf(w1, v1.z, acc.z); acc.w = fmaf(w1, v1.w, acc.w);
    }
    if (idx < e) {
        int   j0 = g_src[idx];
        float w0 = g_wgt[idx];
        float4 v0 = ((const float4*)(vin + (size_t)j0 * 128))[lane];
        acc.x = fmaf(w0, v0.x, acc.x); acc.y = fmaf(w0, v0.y, acc.y);
        acc.z = fmaf(w0, v0.z, acc.z); acc.w = fmaf(w0, v0.w, acc.w);
    }
    ((float4*)(vout + (size_t)node * 128))[lane] = acc;
}

// ---------------- launch ----------------
extern "C" void kernel_launch(void* const* d_in, const int* in_sizes, int n_in,
                              void* d_out, int out_size) {
    const float* x   = (const float*)d_in[0];
    const int*   ei  = (const int*)  d_in[1];
    const float* ea  = (const float*)d_in[2];
    const float* W1  = (const float*)d_in[3];
    const float* b1  = (const float*)d_in[4];
    const float* W2  = (const float*)d_in[5];
    const float* b2  = (const float*)d_in[6];
    const float* t0W = (const float*)d_in[7];
    const float* t0b = (const float*)d_in[8];
    const float* t1W = (const float*)d_in[9];
    const float* t1b = (const float*)d_in[10];
    const float* t2W = (const float*)d_in[11];
    const float* t2b = (const float*)d_in[12];
    const int* row = ei;        // source j
    const int* col = ei + Ee;   // target i

    float *ph, *pa, *pp1, *pp2, *pp3, *pdeg;
    unsigned char* pwb;
    cudaGetSymbolAddress((void**)&ph,   g_h);
    cudaGetSymbolAddress((void**)&pa,   g_a);
    cudaGetSymbolAddress((void**)&pp1,  g_p1);
    cudaGetSymbolAddress((void**)&pp2,  g_p2);
    cudaGetSymbolAddress((void**)&pp3,  g_p3);
    cudaGetSymbolAddress((void**)&pdeg, g_degf);
    cudaGetSymbolAddress((void**)&pwb,  g_wbf);

    const int SMEM128 = 2 * A_SPLIT_BYTES + 2 * 128 * 256;  // 69632 + 65536 = 135168
    const int SMEM64  = 2 * A_SPLIT_BYTES + 2 * 64 * 256;   // 69632 + 32768 = 102400
    cudaFuncSetAttribute(tc_gemm<1, 128, 0, 1>, cudaFuncAttributeMaxDynamicSharedMemorySize, SMEM128);
    cudaFuncSetAttribute(tc_gemm<1, 128, 0, 0>, cudaFuncAttributeMaxDynamicSharedMemorySize, SMEM128);
    cudaFuncSetAttribute(tc_gemm<1, 128, 0, 2>, cudaFuncAttributeMaxDynamicSharedMemorySize, SMEM128);
    cudaFuncSetAttribute(tc_gemm<4, 128, 1, 1>, cudaFuncAttributeMaxDynamicSharedMemorySize, SMEM128);
    cudaFuncSetAttribute(tc_gemm<4, 64, 0, 1>,  cudaFuncAttributeMaxDynamicSharedMemorySize, SMEM64);

    const int TC_GRID   = (Nn + 127) / 128;   // 391
    const int WARP_GRID = (Nn * 32 + 255) / 256;
    const int SPMM_GRID = (Nn + 3) / 4;

    // prep + P/Q node GEMMs (4th launch = profiled slot -> tc_gemm P)
    init_kernel<<<(Nn + 255) / 256, 256>>>();
    count_kernel<<<Ee / 256, 256>>>(col);
    wprep_kernel<<<(212992 + 255) / 256, 256>>>(W1, W2, t0W, t1W, t2W);
    tc_gemm<1, 128, 0, 1><<<TC_GRID, 256, SMEM128>>>(x, x, x, x, pwb + OFF_W1A, b1, nullptr, pp1);
    tc_gemm<1, 128, 0, 0><<<TC_GRID, 256, SMEM128>>>(x, x, x, x, pwb + OFF_W1B, nullptr, nullptr, pp2);
    scan_dis_kernel<<<1, 1024>>>();
    scatter_kernel<<<Ee / 256, 256>>>(row, col);

    // S = per-target aggregated hidden; h = S*W2 + deg*b2
    agg_kernel<<<WARP_GRID, 256>>>(pp1, pp2, ea, W1 + 256 * 128, pp3);
    tc_gemm<1, 128, 0, 2><<<TC_GRID, 256, SMEM128>>>(pp3, pp3, pp3, pp3, pwb + OFF_W2, b2, pdeg, ph);

    // layer 0: h -> a  (ReLU)
    spmm_kernel<<<SPMM_GRID, 128>>>(ph,  pp1);
    spmm_kernel<<<SPMM_GRID, 128>>>(pp1, pp2);
    spmm_kernel<<<SPMM_GRID, 128>>>(pp2, pp3);
    tc_gemm<4, 128, 1, 1><<<TC_GRID, 256, SMEM128>>>(ph, pp1, pp2, pp3, pwb + OFF_T0, t0b, nullptr, pa);

    // layer 1: a -> h  (ReLU)
    spmm_kernel<<<SPMM_GRID, 128>>>(pa,  pp1);
    spmm_kernel<<<SPMM_GRID, 128>>>(pp1, pp2);
    spmm_kernel<<<SPMM_GRID, 128>>>(pp2, pp3);
    tc_gemm<4, 128, 1, 1><<<TC_GRID, 256, SMEM128>>>(pa, pp1, pp2, pp3, pwb + OFF_T1, t1b, nullptr, ph);

    // layer 2: h -> out (no ReLU, C=64)
    spmm_kernel<<<SPMM_GRID, 128>>>(ph,  pp1);
    spmm_kernel<<<SPMM_GRID, 128>>>(pp1, pp2);
    spmm_kernel<<<SPMM_GRID, 128>>>(pp2, pp3);
    tc_gemm<4, 64, 0, 1><<<TC_GRID, 256, SMEM64>>>(ph, pp1, pp2, pp3, pwb + OFF_T2, t2b, nullptr, (float*)d_out);
}

// round 9
// speedup vs baseline: 22.2272x; 1.1860x over previous
#include <cuda_runtime.h>
#include <cuda_bf16.h>
#include <math.h>

typedef unsigned long long ull;

#define Nn   50000
#define Ee   800000

// ---------------- scratch (static device memory; no allocations) ----------------
__device__ float g_h [Nn * 128];
__device__ float g_u0[Nn * 128];
__device__ float g_u1[Nn * 128];
__device__ float g_u2[Nn * 128];
__device__ float g_u3[Nn * 128];
__device__ float g_t1[Nn * 128];
__device__ float g_t2[Nn * 128];
__device__ float g_dis[Nn];
__device__ float g_degf[Nn];
__device__ int   g_cnt[Nn];
__device__ int   g_cur[Nn];
__device__ int   g_off[Nn + 1];
__device__ int   g_src[Ee];
__device__ int   g_eid[Ee];
__device__ float g_wgt[Ee];

// bf16 hi/lo weight fragment images (mma.sync per-thread order)
#define OFF_W1A 0
#define OFF_W1B 65536
#define OFF_W2  131072
#define OFF_T0  196608
#define OFF_T1  458752
#define OFF_T2  720896
__device__ __align__(16) unsigned char g_wbf[851968];

// ---------------- setup kernels ----------------
__global__ void init_kernel() {
    int i = blockIdx.x * blockDim.x + threadIdx.x;
    if (i < Nn) { g_cnt[i] = 0; g_cur[i] = 0; }
}

__global__ void count_kernel(const int* __restrict__ col) {
    int e = blockIdx.x * blockDim.x + threadIdx.x;
    if (e < Ee) atomicAdd(&g_cnt[col[e]], 1);
}

__global__ void scan_dis_kernel() {
    __shared__ int sm[1024];
    __shared__ int carry;
    int tid = threadIdx.x;
    if (tid == 0) { carry = 0; g_off[0] = 0; }
    __syncthreads();
    for (int base = 0; base < Nn; base += 1024) {
        int i = base + tid;
        int v = (i < Nn) ? g_cnt[i] : 0;
        sm[tid] = v;
        __syncthreads();
        for (int s = 1; s < 1024; s <<= 1) {
            int t = (tid >= s) ? sm[tid - s] : 0;
            __syncthreads();
            sm[tid] += t;
            __syncthreads();
        }
        if (i < Nn) {
            g_off[i + 1] = carry + sm[tid];
            g_dis[i]  = (v > 0) ? rsqrtf((float)v) : 0.0f;
            g_degf[i] = (float)v;
        }
        __syncthreads();
        if (tid == 1023) carry += sm[1023];
        __syncthreads();
    }
}

__global__ void scatter_kernel(const int* __restrict__ row, const int* __restrict__ col) {
    int e = blockIdx.x * blockDim.x + threadIdx.x;
    if (e < Ee) {
        int i = col[e], j = row[e];
        int p = atomicAdd(&g_cur[i], 1);
        int o = g_off[i] + p;
        g_src[o] = j;
        g_eid[o] = e;
        g_wgt[o] = g_dis[i] * g_dis[j];
    }
}

// ---------------- weight prep: fp32 [K=128][C] -> bf16 hi/lo mma fragment images ----
__global__ void wprep_kernel(const float* __restrict__ W1, const float* __restrict__ W2,
                             const float* __restrict__ t0W, const float* __restrict__ t1W,
                             const float* __restrict__ t2W) {
    int idx = blockIdx.x * blockDim.x + threadIdx.x;
    const int total = 212992;
    if (idx >= total) return;
    const float* src; unsigned char* dst; int C, e;
    if (idx < 16384)       { src = W1;         dst = g_wbf + OFF_W1A; C = 128; e = idx; }
    else if (idx < 32768)  { src = W1 + 16384; dst = g_wbf + OFF_W1B; C = 128; e = idx - 16384; }
    else if (idx < 49152)  { src = W2;         dst = g_wbf + OFF_W2;  C = 128; e = idx - 32768; }
    else if (idx < 114688) { src = t0W;        dst = g_wbf + OFF_T0;  C = 128; e = idx - 49152; }
    else if (idx < 180224) { src = t1W;        dst = g_wbf + OFF_T1;  C = 128; e = idx - 114688; }
    else                   { src = t2W;        dst = g_wbf + OFF_T2;  C = 64;  e = idx - 180224; }
    int per = 128 * C;
    int g = e / per, r = e - g * per;
    int k = r / C, n = r - k * C;
    float v = src[(size_t)g * per + (size_t)k * C + n];
    __nv_bfloat16 hi = __float2bfloat16(v);
    __nv_bfloat16 lo = __float2bfloat16(v - __bfloat162float(hi));
    int TB = C * 256;
    int NT = C >> 3;
    int kstep = k >> 4, kin = k & 15, reg = kin >> 3, kb = kin & 7;
    int lane = (n & 7) * 4 + (kb >> 1);
    int off = (((kstep * NT + (n >> 3)) * 32 + lane) << 3) + reg * 4 + (kb & 1) * 2;
    *(__nv_bfloat16*)(dst + (size_t)g * 2 * TB + off)      = hi;
    *(__nv_bfloat16*)(dst + (size_t)g * 2 * TB + TB + off) = lo;
}

// ---------------- mma.sync helper ----------------
__device__ __forceinline__ void mma16816(float& c0, float& c1, float& c2, float& c3,
                                         unsigned a0, unsigned a1, unsigned a2, unsigned a3,
                                         unsigned b0, unsigned b1) {
    asm volatile(
        "mma.sync.aligned.m16n8k16.row.col.f32.bf16.bf16.f32 "
        "{%0,%1,%2,%3}, {%4,%5,%6,%7}, {%8,%9}, {%0,%1,%2,%3};"
        : "+f"(c0), "+f"(c1), "+f"(c2), "+f"(c3)
        : "r"(a0), "r"(a1), "r"(a2), "r"(a3), "r"(b0), "r"(b1));
}

// ---------------- multi-output tensor-core GEMM (shared A tile) ----------------
// o_k[128tile, C] = A * W_k for k < NK. B fragments streamed from gmem (L1/L2 hot).
// BMODE: 0 none, 1 bias on output 0 only, 2 deg[row]*bias (NK==1)
#define AST 136
#define A_SPLIT_BYTES (128 * AST * 2)   // 34816
#define TC_SMEM (2 * A_SPLIT_BYTES)     // 69632
template <int NK, int C, int BMODE>
__global__ void __launch_bounds__(256, 2)
tc_gemm(const float* __restrict__ A, const unsigned char* __restrict__ Wt,
        const float* __restrict__ bias, const float* __restrict__ degf,
        float* __restrict__ o0, float* __restrict__ o1,
        float* __restrict__ o2, float* __restrict__ o3) {
    extern __shared__ __align__(16) unsigned char sm[];
    __nv_bfloat16* Ah = (__nv_bfloat16*)sm;
    __nv_bfloat16* Al = (__nv_bfloat16*)(sm + A_SPLIT_BYTES);
    constexpr int NT = C / 8;
    constexpr int TB = C * 256;
    const int tid = threadIdx.x, wid = tid >> 5, lane = tid & 31;
    const int row0 = blockIdx.x * 128;

    // ---- convert A tile (128 rows x 128 k fp32) -> bf16 hi/lo row-major ----
    {
        int r  = tid >> 1;
        int kh = tid & 1;
        int grow = row0 + r;
        const float* src = A + (size_t)grow * 128 + kh * 64;
        __nv_bfloat16* hp = Ah + r * AST + kh * 64;
        __nv_bfloat16* lp = Al + r * AST + kh * 64;
#pragma unroll
        for (int q = 0; q < 16; q++) {
            float4 v = (grow < Nn) ? *(const float4*)(src + q * 4)
                                   : make_float4(0.f, 0.f, 0.f, 0.f);
            __nv_bfloat16 hx = __float2bfloat16(v.x);
            __nv_bfloat16 hy = __float2bfloat16(v.y);
            __nv_bfloat16 hz = __float2bfloat16(v.z);
            __nv_bfloat16 hw = __float2bfloat16(v.w);
            __nv_bfloat162 h01; h01.x = hx; h01.y = hy;
            __nv_bfloat162 h23; h23.x = hz; h23.y = hw;
            __nv_bfloat162 l01, l23;
            l01.x = __float2bfloat16(v.x - __bfloat162float(hx));
            l01.y = __float2bfloat16(v.y - __bfloat162float(hy));
            l23.x = __float2bfloat16(v.z - __bfloat162float(hz));
            l23.y = __float2bfloat16(v.w - __bfloat162float(hw));
            *(__nv_bfloat162*)(hp + q * 4)     = h01;
            *(__nv_bfloat162*)(hp + q * 4 + 2) = h23;
            *(__nv_bfloat162*)(lp + q * 4)     = l01;
            *(__nv_bfloat162*)(lp + q * 4 + 2) = l23;
        }
    }
    __syncthreads();

    float* outs[4] = {o0, o1, o2, o3};
    const int m0 = wid * 16 + (lane >> 2);
    const int kq = (lane & 3) * 2;
    const int mA = row0 + m0, mB = mA + 8;
    float dgA = 1.f, dgB = 1.f;
    if (BMODE == 2) {
        dgA = (mA < Nn) ? degf[mA] : 0.f;
        dgB = (mB < Nn) ? degf[mB] : 0.f;
    }

#pragma unroll
    for (int kk = 0; kk < NK; kk++) {
        float acc[NT][4];
#pragma unroll
        for (int nt = 0; nt < NT; nt++)
#pragma unroll
            for (int c = 0; c < 4; c++) acc[nt][c] = 0.f;

        const unsigned char* Bk = Wt + (size_t)kk * 2 * TB;
#pragma unroll 1
        for (int ks = 0; ks < 8; ks++) {
            int k0 = ks * 16 + kq;
            unsigned aH0 = *(const unsigned*)(Ah + m0 * AST + k0);
            unsigned aH1 = *(const unsigned*)(Ah + (m0 + 8) * AST + k0);
            unsigned aH2 = *(const unsigned*)(Ah + m0 * AST + k0 + 8);
            unsigned aH3 = *(const unsigned*)(Ah + (m0 + 8) * AST + k0 + 8);
            unsigned aL0 = *(const unsigned*)(Al + m0 * AST + k0);
            unsigned aL1 = *(const unsigned*)(Al + (m0 + 8) * AST + k0);
            unsigned aL2 = *(const unsigned*)(Al + m0 * AST + k0 + 8);
            unsigned aL3 = *(const unsigned*)(Al + (m0 + 8) * AST + k0 + 8);
            const unsigned char* bbase = Bk + ((size_t)(ks * NT) * 32 + lane) * 8;
#pragma unroll
            for (int nt = 0; nt < NT; nt++) {
                uint2 bh = __ldg((const uint2*)(bbase + nt * 256));
                uint2 bl = __ldg((const uint2*)(bbase + nt * 256 + TB));
                mma16816(acc[nt][0], acc[nt][1], acc[nt][2], acc[nt][3],
                         aH0, aH1, aH2, aH3, bh.x, bh.y);
                mma16816(acc[nt][0], acc[nt][1], acc[nt][2], acc[nt][3],
                         aH0, aH1, aH2, aH3, bl.x, bl.y);
                mma16816(acc[nt][0], acc[nt][1], acc[nt][2], acc[nt][3],
                         aL0, aL1, aL2, aL3, bh.x, bh.y);
            }
        }

        float* out = outs[kk];
        bool ab = (BMODE == 1 && kk == 0) || (BMODE == 2);
#pragma unroll
        for (int nt = 0; nt < NT; nt++) {
            int n0 = nt * 8 + (lane & 3) * 2;
            float bx = 0.f, by = 0.f;
            if (ab) { float2 bv = *(const float2*)(bias + n0); bx = bv.x; by = bv.y; }
            float v0 = acc[nt][0], v1 = acc[nt][1], v2 = acc[nt][2], v3 = acc[nt][3];
            if (BMODE == 1 && kk == 0) { v0 += bx; v1 += by; v2 += bx; v3 += by; }
            if (BMODE == 2) { v0 += dgA * bx; v1 += dgA * by; v2 += dgB * bx; v3 += dgB * by; }
            if (mA < Nn) *(float2*)(out + (size_t)mA * C + n0) = make_float2(v0, v1);
            if (mB < Nn) *(float2*)(out + (size_t)mB * C + n0) = make_float2(v2, v3);
        }
    }
}

// ---------------- agg kernel: S_i = sum_{e in CSR[i]} relu(P_i + Q_{j_e} + ea_e*W1c) ----
__global__ void __launch_bounds__(256)
agg_kernel(const float* __restrict__ P, const float* __restrict__ Q,
           const float* __restrict__ ea,
           const float* __restrict__ W1c,   // [16][128]
           float* __restrict__ S) {
    int i    = (blockIdx.x * blockDim.x + threadIdx.x) >> 5;
    int lane = threadIdx.x & 31;
    if (i >= Nn) return;

    float4 w1c[16];
#pragma unroll
    for (int k = 0; k < 16; k++)
        w1c[k] = __ldg((const float4*)(W1c + (size_t)k * 128) + lane);

    float4 p = *(const float4*)(P + (size_t)i * 128 + lane * 4);
    float4 acc = make_float4(0.f, 0.f, 0.f, 0.f);

    int s = g_off[i], e = g_off[i + 1];
#pragma unroll 2
    for (int t = s; t < e; t++) {
        int j   = g_src[t];
        int eid = g_eid[t];
        const float4* eb = (const float4*)(ea + (size_t)eid * 16);
        float4 e0 = __ldg(eb + 0), e1 = __ldg(eb + 1);
        float4 e2 = __ldg(eb + 2), e3 = __ldg(eb + 3);
        float4 q = __ldg((const float4*)(Q + (size_t)j * 128) + lane);
        float4 c;
        c.x = p.x + q.x; c.y = p.y + q.y; c.z = p.z + q.z; c.w = p.w + q.w;
        const float ks[16] = { e0.x, e0.y, e0.z, e0.w, e1.x, e1.y, e1.z, e1.w,
                               e2.x, e2.y, e2.z, e2.w, e3.x, e3.y, e3.z, e3.w };
#pragma unroll
        for (int k = 0; k < 16; k++) {
            c.x = fmaf(ks[k], w1c[k].x, c.x);
            c.y = fmaf(ks[k], w1c[k].y, c.y);
            c.z = fmaf(ks[k], w1c[k].z, c.z);
            c.w = fmaf(ks[k], w1c[k].w, c.w);
        }
        acc.x += fmaxf(c.x, 0.f);
        acc.y += fmaxf(c.y, 0.f);
        acc.z += fmaxf(c.z, 0.f);
        acc.w += fmaxf(c.w, 0.f);
    }
    *(float4*)(S + (size_t)i * 128 + lane * 4) = acc;
}

// ---------------- fused SpMM: out_i = [relu]( add_i [+ b] + sum_e w_e * vin[src_e] ) ----
template <int C, int RELU, int BIAS>
__global__ void __launch_bounds__(128)
spmm_kernel(const float* __restrict__ vin, const float* __restrict__ addv,
            const float* __restrict__ bias, float* __restrict__ vout) {
    int node = (blockIdx.x * blockDim.x + threadIdx.x) >> 5;
    int lane = threadIdx.x & 31;
    if (node >= Nn) return;
    int s = g_off[node], e = g_off[node + 1];

    if (C == 128) {
        float4 acc = ((const float4*)(addv + (size_t)node * 128))[lane];
        if (BIAS) {
            float4 b = *(const float4*)(bias + lane * 4);
            acc.x += b.x; acc.y += b.y; acc.z += b.z; acc.w += b.w;
        }
        int idx = s;
        for (; idx + 1 < e; idx += 2) {
            int   j0 = g_src[idx],     j1 = g_src[idx + 1];
            float w0 = g_wgt[idx],     w1 = g_wgt[idx + 1];
            float4 v0 = ((const float4*)(vin + (size_t)j0 * 128))[lane];
            float4 v1 = ((const float4*)(vin + (size_t)j1 * 128))[lane];
            acc.x = fmaf(w0, v0.x, acc.x); acc.y = fmaf(w0, v0.y, acc.y);
            acc.z = fmaf(w0, v0.z, acc.z); acc.w = fmaf(w0, v0.w, acc.w);
            acc.x = fmaf(w1, v1.x, acc.x); acc.y = fmaf(w1, v1.y, acc.y);
            acc.z = fmaf(w1, v1.z, acc.z); acc.w = fmaf(w1, v1.w, acc.w);
        }
        if (idx < e) {
            int   j0 = g_src[idx];
            float w0 = g_wgt[idx];
            float4 v0 = ((const float4*)(vin + (size_t)j0 * 128))[lane];
            acc.x = fmaf(w0, v0.x, acc.x); acc.y = fmaf(w0, v0.y, acc.y);
            acc.z = fmaf(w0, v0.z, acc.z); acc.w = fmaf(w0, v0.w, acc.w);
        }
        if (RELU) {
            acc.x = fmaxf(acc.x, 0.f); acc.y = fmaxf(acc.y, 0.f);
            acc.z = fmaxf(acc.z, 0.f); acc.w = fmaxf(acc.w, 0.f);
        }
        ((float4*)(vout + (size_t)node * 128))[lane] = acc;
    } else {
        float2 acc = ((const float2*)(addv + (size_t)node * 64))[lane];
        if (BIAS) {
            float2 b = *(const float2*)(bias + lane * 2);
            acc.x += b.x; acc.y += b.y;
        }
        int idx = s;
        for (; idx + 1 < e; idx += 2) {
            int   j0 = g_src[idx],     j1 = g_src[idx + 1];
            float w0 = g_wgt[idx],     w1 = g_wgt[idx + 1];
            float2 v0 = ((const float2*)(vin + (size_t)j0 * 64))[lane];
            float2 v1 = ((const float2*)(vin + (size_t)j1 * 64))[lane];
            acc.x = fmaf(w0, v0.x, acc.x); acc.y = fmaf(w0, v0.y, acc.y);
            acc.x = fmaf(w1, v1.x, acc.x); acc.y = fmaf(w1, v1.y, acc.y);
        }
        if (idx < e) {
            int   j0 = g_src[idx];
            float w0 = g_wgt[idx];
            float2 v0 = ((const float2*)(vin + (size_t)j0 * 64))[lane];
            acc.x = fmaf(w0, v0.x, acc.x); acc.y = fmaf(w0, v0.y, acc.y);
        }
        if (RELU) { acc.x = fmaxf(acc.x, 0.f); acc.y = fmaxf(acc.y, 0.f); }
        ((float2*)(vout + (size_t)node * 64))[lane] = acc;
    }
}

// ---------------- launch ----------------
extern "C" void kernel_launch(void* const* d_in, const int* in_sizes, int n_in,
                              void* d_out, int out_size) {
    const float* x   = (const float*)d_in[0];
    const int*   ei  = (const int*)  d_in[1];
    const float* ea  = (const float*)d_in[2];
    const float* W1  = (const float*)d_in[3];
    const float* b1  = (const float*)d_in[4];
    const float* W2  = (const float*)d_in[5];
    const float* b2  = (const float*)d_in[6];
    const float* t0W = (const float*)d_in[7];
    const float* t0b = (const float*)d_in[8];
    const float* t1W = (const float*)d_in[9];
    const float* t1b = (const float*)d_in[10];
    const float* t2W = (const float*)d_in[11];
    const float* t2b = (const float*)d_in[12];
    const int* row = ei;        // source j
    const int* col = ei + Ee;   // target i

    float *ph, *pu0, *pu1, *pu2, *pu3, *pt1, *pt2, *pdeg;
    unsigned char* pwb;
    cudaGetSymbolAddress((void**)&ph,   g_h);
    cudaGetSymbolAddress((void**)&pu0,  g_u0);
    cudaGetSymbolAddress((void**)&pu1,  g_u1);
    cudaGetSymbolAddress((void**)&pu2,  g_u2);
    cudaGetSymbolAddress((void**)&pu3,  g_u3);
    cudaGetSymbolAddress((void**)&pt1,  g_t1);
    cudaGetSymbolAddress((void**)&pt2,  g_t2);
    cudaGetSymbolAddress((void**)&pdeg, g_degf);
    cudaGetSymbolAddress((void**)&pwb,  g_wbf);

    cudaFuncSetAttribute(tc_gemm<2, 128, 1>, cudaFuncAttributeMaxDynamicSharedMemorySize, TC_SMEM);
    cudaFuncSetAttribute(tc_gemm<1, 128, 2>, cudaFuncAttributeMaxDynamicSharedMemorySize, TC_SMEM);
    cudaFuncSetAttribute(tc_gemm<4, 128, 0>, cudaFuncAttributeMaxDynamicSharedMemorySize, TC_SMEM);
    cudaFuncSetAttribute(tc_gemm<4, 64, 0>,  cudaFuncAttributeMaxDynamicSharedMemorySize, TC_SMEM);

    const int TC_GRID   = (Nn + 127) / 128;   // 391
    const int WARP_GRID = (Nn * 32 + 255) / 256;
    const int SPMM_GRID = (Nn + 3) / 4;

    // prep (4th launch = profiled slot -> tc_gemm P/Q)
    init_kernel<<<(Nn + 255) / 256, 256>>>();
    count_kernel<<<Ee / 256, 256>>>(col);
    wprep_kernel<<<(212992 + 255) / 256, 256>>>(W1, W2, t0W, t1W, t2W);
    tc_gemm<2, 128, 1><<<TC_GRID, 256, TC_SMEM>>>(x, pwb + OFF_W1A, b1, nullptr,
                                                  pu0, pu1, nullptr, nullptr);
    scan_dis_kernel<<<1, 1024>>>();
    scatter_kernel<<<Ee / 256, 256>>>(row, col);

    // S = aggregated hidden (u2); h = S*W2 + deg*b2
    agg_kernel<<<WARP_GRID, 256>>>(pu0, pu1, ea, W1 + 256 * 128, pu2);
    tc_gemm<1, 128, 2><<<TC_GRID, 256, TC_SMEM>>>(pu2, pwb + OFF_W2, b2, pdeg,
                                                  ph, nullptr, nullptr, nullptr);

    // layer 0 (Horner): U_k = h*W_k; h' = relu(U0 + A(U1 + A(U2 + A U3)) + b)
    tc_gemm<4, 128, 0><<<TC_GRID, 256, TC_SMEM>>>(ph, pwb + OFF_T0, nullptr, nullptr,
                                                  pu0, pu1, pu2, pu3);
    spmm_kernel<128, 0, 0><<<SPMM_GRID, 128>>>(pu3, pu2, nullptr, pt1);
    spmm_kernel<128, 0, 0><<<SPMM_GRID, 128>>>(pt1, pu1, nullptr, pt2);
    spmm_kernel<128, 1, 1><<<SPMM_GRID, 128>>>(pt2, pu0, t0b, ph);

    // layer 1
    tc_gemm<4, 128, 0><<<TC_GRID, 256, TC_SMEM>>>(ph, pwb + OFF_T1, nullptr, nullptr,
                                                  pu0, pu1, pu2, pu3);
    spmm_kernel<128, 0, 0><<<SPMM_GRID, 128>>>(pu3, pu2, nullptr, pt1);
    spmm_kernel<128, 0, 0><<<SPMM_GRID, 128>>>(pt1, pu1, nullptr, pt2);
    spmm_kernel<128, 1, 1><<<SPMM_GRID, 128>>>(pt2, pu0, t1b, ph);

    // layer 2 (C=64, no relu)
    tc_gemm<4, 64, 0><<<TC_GRID, 256, TC_SMEM>>>(ph, pwb + OFF_T2, nullptr, nullptr,
                                                 pu0, pu1, pu2, pu3);
    spmm_kernel<64, 0, 0><<<SPMM_GRID, 128>>>(pu3, pu2, nullptr, pt1);
    spmm_kernel<64, 0, 0><<<SPMM_GRID, 128>>>(pt1, pu1, nullptr, pt2);
    spmm_kernel<64, 0, 1><<<SPMM_GRID, 128>>>(pt2, pu0, t2b, (float*)d_out);
}